// round 12
// baseline (speedup 1.0000x reference)
#include <cuda_runtime.h>
#include <cuda_bf16.h>
#include <cuda_fp16.h>
#include <cstdint>
#include <math.h>

#define BB 16
#define LL 512
#define TT 128
#define VV 21128
#define DD 512

// packed fp32x2 helpers (scalar gemm + lstm)
#define PACK2(d, a, b)  asm("mov.b64 %0, {%1,%2};" : "=l"(d) : "f"(a), "f"(b))
#define FMA2(acc, a, b) asm("fma.rn.f32x2 %0, %1, %2, %3;" : "=l"(acc) : "l"(a), "l"(b), "l"(acc))
#define UNPACK2(lo, hi, p) asm("mov.b64 {%0,%1}, %2;" : "=f"(lo), "=f"(hi) : "l"(p))

// ---------------------------------------------------------------------------
// Device scratch
// ---------------------------------------------------------------------------
__device__ __align__(16) float g_emb[BB * LL * DD];
__device__ __align__(16) float g_Wcat[4096 * 512];
__device__ __align__(16) float g_bcat[4096];
__device__ __align__(16) float g_xg[8192 * 4096];
__device__ __align__(16) float g_encf[BB * LL * DD];
__device__ __align__(16) float g_encb[BB * LL * DD];
__device__ __align__(16) float g_hbuf[2 * 2 * BB * DD];
__device__ __align__(16) float g_hT[BB * 1024];
__device__ __align__(16) float g_hidden[BB * DD];
__device__ __align__(16) float g_Xatt[8192 * 1536];
__device__ __align__(16) float g_energy[8192 * 512];
__device__ __align__(16) float g_att[8192];
__device__ __align__(16) float g_a[8192];
__device__ __align__(16) float g_weighted[BB * 1024];
__device__ __align__(16) float g_embs[2032 * 512];
__device__ __align__(16) float g_Xdec[2032 * 1536];
__device__ __align__(16) float g_dbias[2048];
__device__ __align__(16) float g_dg[2032 * 2048];
__device__ __align__(16) float g_dech[2032 * 512];
__device__ __align__(16) float g_Xpred[2032 * 2048];
__device__ __align__(16) float g_pred[2032 * VV];
__device__ float g_nll[2032];
// 4 barrier counters at 128B stride: [dir*2 + half] * 32
__device__ __align__(128) unsigned g_bar4[4 * 32];

__device__ __forceinline__ float sigf(float x) { return 1.0f / (1.0f + expf(-x)); }

__device__ __forceinline__ unsigned smem_u32(const void* p)
{
    unsigned a;
    asm("{ .reg .u64 t; cvta.to.shared.u64 t, %1; cvt.u32.u64 %0, t; }" : "=r"(a) : "l"(p));
    return a;
}

#define LDSM_X4(r0, r1, r2, r3, addr) \
    asm volatile("ldmatrix.sync.aligned.m8n8.x4.shared.b16 {%0,%1,%2,%3}, [%4];" \
                 : "=r"(r0), "=r"(r1), "=r"(r2), "=r"(r3) : "r"(addr))

#define MMA_F16(c, a, b) \
    asm volatile("mma.sync.aligned.m16n8k16.row.col.f32.f16.f16.f32 " \
                 "{%0,%1,%2,%3}, {%4,%5,%6,%7}, {%8,%9}, {%0,%1,%2,%3};" \
                 : "+f"((c)[0]), "+f"((c)[1]), "+f"((c)[2]), "+f"((c)[3]) \
                 : "r"((a)[0]), "r"((a)[1]), "r"((a)[2]), "r"((a)[3]), \
                   "r"((b)[0]), "r"((b)[1]))

// split fp32x4 -> fp16x4 hi (uint2) + fp16x4 lo (uint2)   [A operand]
__device__ __forceinline__ void split4h(const float4& v, uint2& h, uint2& l)
{
    __half2 h01 = __floats2half2_rn(v.x, v.y);
    __half2 h23 = __floats2half2_rn(v.z, v.w);
    float2 f01 = __half22float2(h01);
    float2 f23 = __half22float2(h23);
    __half2 l01 = __floats2half2_rn(v.x - f01.x, v.y - f01.y);
    __half2 l23 = __floats2half2_rn(v.z - f23.x, v.w - f23.y);
    h = make_uint2(*(unsigned*)&h01, *(unsigned*)&h23);
    l = make_uint2(*(unsigned*)&l01, *(unsigned*)&l23);
}

// fp32x4 -> fp16x4 hi only   [B operand]
__device__ __forceinline__ uint2 cvt4h(const float4& v)
{
    __half2 h01 = __floats2half2_rn(v.x, v.y);
    __half2 h23 = __floats2half2_rn(v.z, v.w);
    return make_uint2(*(unsigned*)&h01, *(unsigned*)&h23);
}

// ---------------------------------------------------------------------------
// fp16 split-precision warp-mma GEMM (2 passes):
//   C[M,N] = (A_hi + A_lo)[M,K] @ B_hi[N,K]^T + bias
//   mode 0: plain   1: tanh
// ---------------------------------------------------------------------------
__global__ void __launch_bounds__(256, 1)
gemm_mma_kernel(const float* __restrict__ A, const float* __restrict__ Bw,
                const float* __restrict__ bias, float* __restrict__ C,
                int M, int N, int K, int mode)
{
    extern __shared__ __align__(16) char smem[];
    const unsigned sbase = smem_u32(smem);
    const unsigned OFF_AH = 0, OFF_AL = 18432, OFF_BH = 36864;

    const int tid  = threadIdx.x;
    const int wid  = tid >> 5;
    const int lane = tid & 31;
    const int wm   = wid >> 2;
    const int wn   = wid & 3;
    const int row0 = blockIdx.x * 128;
    const int col0 = blockIdx.y * 128;

    float acc[4][4][4];
#pragma unroll
    for (int i = 0; i < 4; i++)
#pragma unroll
        for (int j = 0; j < 4; j++)
#pragma unroll
            for (int q = 0; q < 4; q++) acc[i][j][q] = 0.0f;

    const int a_lr = lane & 15, a_lh = lane >> 4;
    const int b_g = lane >> 3, b_l8 = lane & 7;
    const int b_rofs = (b_g >> 1) * 8 + b_l8;
    const int b_cofs = (b_g & 1) * 8;

    int srow[8], scol[8];
#pragma unroll
    for (int i = 0; i < 8; i++) {
        int idx = tid + (i << 8);
        srow[i] = idx >> 4;
        scol[i] = (idx & 15) << 2;
    }

    const float4 zf = make_float4(0.f, 0.f, 0.f, 0.f);
    float4 pa[8], pb[8];
#pragma unroll
    for (int i = 0; i < 8; i++) {
        int ar = row0 + srow[i];
        pa[i] = (ar < M) ? *(const float4*)(A + (size_t)ar * K + scol[i]) : zf;
        int br = col0 + srow[i];
        pb[i] = (br < N) ? *(const float4*)(Bw + (size_t)br * K + scol[i]) : zf;
    }

    const int nch = K >> 6;
    for (int kc = 0; kc < nch; kc++) {
        __syncthreads();
#pragma unroll
        for (int i = 0; i < 8; i++) {
            unsigned so = srow[i] * 144 + scol[i] * 2;
            uint2 h, l;
            split4h(pa[i], h, l);
            *(uint2*)(smem + OFF_AH + so) = h;
            *(uint2*)(smem + OFF_AL + so) = l;
            *(uint2*)(smem + OFF_BH + so) = cvt4h(pb[i]);
        }
        __syncthreads();

        if (kc + 1 < nch) {
            const int k0 = (kc + 1) << 6;
#pragma unroll
            for (int i = 0; i < 8; i++) {
                int ar = row0 + srow[i];
                pa[i] = (ar < M) ? *(const float4*)(A + (size_t)ar * K + k0 + scol[i]) : zf;
                int br = col0 + srow[i];
                pb[i] = (br < N) ? *(const float4*)(Bw + (size_t)br * K + k0 + scol[i]) : zf;
            }
        }

#pragma unroll
        for (int k16 = 0; k16 < 4; k16++) {
            const int kb = k16 << 4;
            unsigned aH[4][4], aL[4][4], bH[4][2];
#pragma unroll
            for (int i = 0; i < 4; i++) {
                unsigned rm = (unsigned)(wm * 64 + i * 16 + a_lr);
                unsigned off = rm * 144 + (unsigned)(kb + a_lh * 8) * 2;
                LDSM_X4(aH[i][0], aH[i][1], aH[i][2], aH[i][3], sbase + OFF_AH + off);
                LDSM_X4(aL[i][0], aL[i][1], aL[i][2], aL[i][3], sbase + OFF_AL + off);
            }
#pragma unroll
            for (int j2 = 0; j2 < 2; j2++) {
                unsigned rn = (unsigned)(wn * 32 + j2 * 16 + b_rofs);
                unsigned off = rn * 144 + (unsigned)(kb + b_cofs) * 2;
                LDSM_X4(bH[2 * j2][0], bH[2 * j2][1], bH[2 * j2 + 1][0], bH[2 * j2 + 1][1],
                        sbase + OFF_BH + off);
            }
#pragma unroll
            for (int i = 0; i < 4; i++)
#pragma unroll
                for (int j = 0; j < 4; j++) {
                    MMA_F16(acc[i][j], aH[i], bH[j]);
                    MMA_F16(acc[i][j], aL[i], bH[j]);
                }
        }
    }

    const int lm = lane >> 2;
    const int ln = (lane & 3) * 2;
#pragma unroll
    for (int i = 0; i < 4; i++) {
#pragma unroll
        for (int j = 0; j < 4; j++) {
            int nbase = col0 + wn * 32 + j * 8 + ln;
#pragma unroll
            for (int half = 0; half < 2; half++) {
                int r = row0 + wm * 64 + i * 16 + lm + half * 8;
                if (r >= M) continue;
                float v0 = acc[i][j][half * 2 + 0];
                float v1 = acc[i][j][half * 2 + 1];
                if (nbase < N) {
                    float v = v0 + __ldg(&bias[nbase]);
                    C[(size_t)r * N + nbase] = (mode == 1) ? tanhf(v) : v;
                }
                if (nbase + 1 < N) {
                    float v = v1 + __ldg(&bias[nbase + 1]);
                    C[(size_t)r * N + nbase + 1] = (mode == 1) ? tanhf(v) : v;
                }
            }
        }
    }
}

// ---------------------------------------------------------------------------
// Transpose g_pred[r= b*127+t-1][v] -> out[b][v][t]
// ---------------------------------------------------------------------------
__global__ void transpose_out_kernel(float* __restrict__ out)
{
    __shared__ float tile[32][33];
    const int b  = blockIdx.z;
    const int v0 = blockIdx.x * 32;
    const int t0 = 1 + blockIdx.y * 32;
    const int tv = threadIdx.x;
    const int tr = threadIdx.y;
#pragma unroll
    for (int i = 0; i < 4; i++) {
        int t = t0 + tr * 4 + i;
        int v = v0 + tv;
        if (t < 128 && v < VV)
            tile[tr * 4 + i][tv] = g_pred[(size_t)(b * 127 + t - 1) * VV + v];
    }
    __syncthreads();
#pragma unroll
    for (int i = 0; i < 4; i++) {
        int v = v0 + tr * 4 + i;
        int t = t0 + tv;
        if (t < 128 && v < VV)
            out[((size_t)b * VV + v) * TT + t] = tile[tv][tr * 4 + i];
    }
}

// ---------------------------------------------------------------------------
// Setup
// ---------------------------------------------------------------------------
__global__ void setup_kernel(const float* __restrict__ Wih_f, const float* __restrict__ Wih_b,
                             const float* __restrict__ bih_f, const float* __restrict__ bhh_f,
                             const float* __restrict__ bih_b, const float* __restrict__ bhh_b,
                             const float* __restrict__ dbih, const float* __restrict__ dbhh,
                             float* __restrict__ out)
{
    int i = blockIdx.x * blockDim.x + threadIdx.x;
    {
        int n  = i >> 7;
        int k4 = (i & 127) << 2;
        const float* W = (n < 2048) ? Wih_f : Wih_b;
        *(float4*)&g_Wcat[(size_t)n * 512 + k4] =
            *(const float4*)&W[(size_t)(n & 2047) * 512 + k4];
    }
    if (i < 4096)
        g_bcat[i] = (i < 2048) ? (bih_f[i] + bhh_f[i]) : (bih_b[i - 2048] + bhh_b[i - 2048]);
    if (i < 2048)
        g_dbias[i] = dbih[i] + dbhh[i];
    if (i < BB * VV)
        out[(size_t)i * TT] = 0.0f;
    if (i < 128) g_bar4[i] = 0u;
}

// ---------------------------------------------------------------------------
// Embedding gathers
// ---------------------------------------------------------------------------
__global__ void embed_doc_kernel(const int* __restrict__ ids, const float* __restrict__ E)
{
    int i = blockIdx.x * blockDim.x + threadIdx.x;
    int m = i >> 7, d4 = (i & 127) << 2;
    int id = ids[m];
    *(float4*)&g_emb[(size_t)m * 512 + d4] = *(const float4*)&E[(size_t)id * 512 + d4];
}

__global__ void embed_sum_kernel(const int* __restrict__ summ, const float* __restrict__ E)
{
    int i = blockIdx.x * blockDim.x + threadIdx.x;
    int m = i >> 7, d4 = (i & 127) << 2;
    int b = m / 127, t = m % 127;
    int id = summ[b * TT + t];
    *(float4*)&g_embs[(size_t)m * 512 + d4] = *(const float4*)&E[(size_t)id * 512 + d4];
}

// ---------------------------------------------------------------------------
// Small scalar GEMM (f32x2) for the 16-row 'hidden' layer
// ---------------------------------------------------------------------------
__global__ void __launch_bounds__(256)
gemm_tn_kernel(const float* __restrict__ A, const float* __restrict__ Bw,
               const float* __restrict__ bias, float* __restrict__ C,
               int M, int N, int K, int mode)
{
    __shared__ __align__(16) float As[2][8 * 132];
    __shared__ __align__(16) float Bs[2][8 * 132];
    const int tid = threadIdx.x;
    const int row0 = blockIdx.y * 128;
    const int col0 = blockIdx.x * 128;
    const int lr = tid >> 1;
    const int lk = (tid & 1) * 4;
    const int ty = tid >> 4, tx = tid & 15;

    unsigned long long acc2[8][4];
#pragma unroll
    for (int i = 0; i < 8; i++)
#pragma unroll
        for (int j = 0; j < 4; j++) acc2[i][j] = 0ULL;

    const int arow = row0 + lr;
    const int brow = col0 + lr;
    const bool aval = arow < M;
    const bool bval = brow < N;
    const float* Aptr = A + (size_t)arow * K + lk;
    const float* Bptr = Bw + (size_t)brow * K + lk;
    const int NT = K >> 3;

    float4 a4 = aval ? *(const float4*)Aptr : make_float4(0.f, 0.f, 0.f, 0.f);
    float4 b4 = bval ? *(const float4*)Bptr : make_float4(0.f, 0.f, 0.f, 0.f);
    As[0][(lk + 0) * 132 + lr] = a4.x; As[0][(lk + 1) * 132 + lr] = a4.y;
    As[0][(lk + 2) * 132 + lr] = a4.z; As[0][(lk + 3) * 132 + lr] = a4.w;
    Bs[0][(lk + 0) * 132 + lr] = b4.x; Bs[0][(lk + 1) * 132 + lr] = b4.y;
    Bs[0][(lk + 2) * 132 + lr] = b4.z; Bs[0][(lk + 3) * 132 + lr] = b4.w;
    __syncthreads();

    for (int t = 0; t < NT; t++) {
        const int cur = t & 1;
        if (t + 1 < NT) {
            a4 = aval ? *(const float4*)(Aptr + (size_t)(t + 1) * 8) : make_float4(0.f, 0.f, 0.f, 0.f);
            b4 = bval ? *(const float4*)(Bptr + (size_t)(t + 1) * 8) : make_float4(0.f, 0.f, 0.f, 0.f);
        }
#pragma unroll
        for (int k = 0; k < 8; k++) {
            float4 x0 = *(const float4*)&As[cur][k * 132 + ty * 8];
            float4 x1 = *(const float4*)&As[cur][k * 132 + ty * 8 + 4];
            float4 y0 = *(const float4*)&Bs[cur][k * 132 + tx * 8];
            float4 y1 = *(const float4*)&Bs[cur][k * 132 + tx * 8 + 4];
            unsigned long long rbp[4];
            PACK2(rbp[0], y0.x, y0.y);
            PACK2(rbp[1], y0.z, y0.w);
            PACK2(rbp[2], y1.x, y1.y);
            PACK2(rbp[3], y1.z, y1.w);
            float ra[8] = {x0.x, x0.y, x0.z, x0.w, x1.x, x1.y, x1.z, x1.w};
#pragma unroll
            for (int i = 0; i < 8; i++) {
                unsigned long long rad;
                PACK2(rad, ra[i], ra[i]);
                FMA2(acc2[i][0], rad, rbp[0]);
                FMA2(acc2[i][1], rad, rbp[1]);
                FMA2(acc2[i][2], rad, rbp[2]);
                FMA2(acc2[i][3], rad, rbp[3]);
            }
        }
        if (t + 1 < NT) {
            const int nxt = cur ^ 1;
            As[nxt][(lk + 0) * 132 + lr] = a4.x; As[nxt][(lk + 1) * 132 + lr] = a4.y;
            As[nxt][(lk + 2) * 132 + lr] = a4.z; As[nxt][(lk + 3) * 132 + lr] = a4.w;
            Bs[nxt][(lk + 0) * 132 + lr] = b4.x; Bs[nxt][(lk + 1) * 132 + lr] = b4.y;
            Bs[nxt][(lk + 2) * 132 + lr] = b4.z; Bs[nxt][(lk + 3) * 132 + lr] = b4.w;
            __syncthreads();
        }
    }

#pragma unroll
    for (int i = 0; i < 8; i++) {
        int r = row0 + ty * 8 + i;
        if (r >= M) continue;
#pragma unroll
        for (int jj = 0; jj < 4; jj++) {
            float lo, hi;
            UNPACK2(lo, hi, acc2[i][jj]);
            float vv[2] = {lo, hi};
#pragma unroll
            for (int q = 0; q < 2; q++) {
                int c = col0 + tx * 8 + jj * 2 + q;
                if (c >= N) continue;
                float v = vv[q] + bias[c];
                C[(size_t)r * N + c] = (mode == 1) ? tanhf(v) : v;
            }
        }
    }
}

// ---------------------------------------------------------------------------
// Persistent bidirectional LSTM.
// Dual 128B-strided arrival counters per direction; per-warp wait + per-warp
// h-slice reload; software-pipelined xg prefetch.
// ---------------------------------------------------------------------------
__global__ void __launch_bounds__(256)
lstm_kernel(const float* __restrict__ Whh_f, const float* __restrict__ Whh_b)
{
    extern __shared__ __align__(16) float sm[];
    float* Whh_s  = sm;                        // 32 x 516
    float* h_s    = sm + 32 * 516;             // 16 x 516
    float* red    = h_s + 16 * 516;            // 512 * 9
    float* gate_s = red + 512 * 9;             // 32 x 16
    float* c_s    = gate_s + 512;              // 128

    const int tid = threadIdx.x;
    const int blk = blockIdx.x;
    const int dir = blk >> 6;
    const int u0  = (blk & 63) * 8;
    const float* Whh = dir ? Whh_b : Whh_f;

    for (int idx = tid; idx < 32 * 512; idx += 256) {
        int lrow = idx >> 9, k = idx & 511;
        int gt = lrow >> 3, j = lrow & 7;
        Whh_s[lrow * 516 + k] = Whh[(size_t)(gt * 512 + u0 + j) * 512 + k];
    }
    for (int idx = tid; idx < 16 * 516; idx += 256) h_s[idx] = 0.0f;
    if (tid < 128) c_s[tid] = 0.0f;
    __syncthreads();

    const int ks   = tid >> 5;        // k-slice == warp id
    const int lane = tid & 31;
    const int rt4  = (lane >> 2) * 4;
    const int bt4  = (lane & 3) * 4;
    const int k0   = ks * 64;

    unsigned* cA  = &g_bar4[(dir * 2 + 0) * 32];
    unsigned* cB  = &g_bar4[(dir * 2 + 1) * 32];
    unsigned* myc = ((blk & 63) < 32) ? cA : cB;

    // prefetch xg for step 0
    float xg0 = 0.f, xg1 = 0.f, xg2 = 0.f, xg3 = 0.f;
    if (tid < 128) {
        const int j = tid & 7, b = tid >> 3;
        const int pos0 = dir ? 511 : 0;
        const size_t xrow = (size_t)(b * 512 + pos0) * 4096 + dir * 2048 + u0 + j;
        xg0 = __ldcg(&g_xg[xrow]);
        xg1 = __ldcg(&g_xg[xrow + 512]);
        xg2 = __ldcg(&g_xg[xrow + 1024]);
        xg3 = __ldcg(&g_xg[xrow + 1536]);
    }

    for (int s = 0; s < 512; s++) {
        const int pos = dir ? (511 - s) : s;

        // prefetch xg for step s+1 (hidden behind matvec+reduce)
        float nx0 = 0.f, nx1 = 0.f, nx2 = 0.f, nx3 = 0.f;
        if (s + 1 < 512 && tid < 128) {
            const int j = tid & 7, b = tid >> 3;
            const int posn = dir ? (511 - (s + 1)) : (s + 1);
            const size_t xrow = (size_t)(b * 512 + posn) * 4096 + dir * 2048 + u0 + j;
            nx0 = __ldcg(&g_xg[xrow]);
            nx1 = __ldcg(&g_xg[xrow + 512]);
            nx2 = __ldcg(&g_xg[xrow + 1024]);
            nx3 = __ldcg(&g_xg[xrow + 1536]);
        }

        unsigned long long acc2[4][2];
#pragma unroll
        for (int j = 0; j < 4; j++) { acc2[j][0] = 0ULL; acc2[j][1] = 0ULL; }

#pragma unroll 4
        for (int kk = 0; kk < 64; kk += 4) {
            const int k = k0 + kk;
            float4 w0 = *(const float4*)&Whh_s[(rt4 + 0) * 516 + k];
            float4 w1 = *(const float4*)&Whh_s[(rt4 + 1) * 516 + k];
            float4 w2 = *(const float4*)&Whh_s[(rt4 + 2) * 516 + k];
            float4 w3 = *(const float4*)&Whh_s[(rt4 + 3) * 516 + k];
            float4 h0 = *(const float4*)&h_s[(bt4 + 0) * 516 + k];
            float4 h1 = *(const float4*)&h_s[(bt4 + 1) * 516 + k];
            float4 h2 = *(const float4*)&h_s[(bt4 + 2) * 516 + k];
            float4 h3 = *(const float4*)&h_s[(bt4 + 3) * 516 + k];
#define LSTM_STEPK(CC)                                                        \
            {                                                                 \
                unsigned long long hp0, hp1, wd;                              \
                PACK2(hp0, h0.CC, h1.CC);                                     \
                PACK2(hp1, h2.CC, h3.CC);                                     \
                PACK2(wd, w0.CC, w0.CC);                                      \
                FMA2(acc2[0][0], wd, hp0); FMA2(acc2[0][1], wd, hp1);         \
                PACK2(wd, w1.CC, w1.CC);                                      \
                FMA2(acc2[1][0], wd, hp0); FMA2(acc2[1][1], wd, hp1);         \
                PACK2(wd, w2.CC, w2.CC);                                      \
                FMA2(acc2[2][0], wd, hp0); FMA2(acc2[2][1], wd, hp1);         \
                PACK2(wd, w3.CC, w3.CC);                                      \
                FMA2(acc2[3][0], wd, hp0); FMA2(acc2[3][1], wd, hp1);         \
            }
            LSTM_STEPK(x)
            LSTM_STEPK(y)
            LSTM_STEPK(z)
            LSTM_STEPK(w)
#undef LSTM_STEPK
        }
#pragma unroll
        for (int j = 0; j < 4; j++)
#pragma unroll
            for (int p = 0; p < 2; p++) {
                float lo, hi;
                UNPACK2(lo, hi, acc2[j][p]);
                red[((rt4 + j) * 16 + bt4 + 2 * p + 0) * 9 + ks] = lo;
                red[((rt4 + j) * 16 + bt4 + 2 * p + 1) * 9 + ks] = hi;
            }
        __syncthreads();

#pragma unroll
        for (int rep = 0; rep < 2; rep++) {
            int p = tid + rep * 256;
            float ssum = 0.0f;
#pragma unroll
            for (int q = 0; q < 8; q++) ssum += red[p * 9 + q];
            gate_s[p] = ssum;
        }
        __syncthreads();

        if (tid < 128) {
            const int j = tid & 7, b = tid >> 3;
            float gi = gate_s[(0 * 8 + j) * 16 + b] + xg0;
            float gf = gate_s[(1 * 8 + j) * 16 + b] + xg1;
            float gg = gate_s[(2 * 8 + j) * 16 + b] + xg2;
            float go = gate_s[(3 * 8 + j) * 16 + b] + xg3;
            float c = sigf(gf) * c_s[tid] + sigf(gi) * tanhf(gg);
            c_s[tid] = c;
            float h = sigf(go) * tanhf(c);
            const int u = u0 + j;
            (dir ? g_encb : g_encf)[(size_t)(b * 512 + pos) * 512 + u] = h;
            g_hbuf[((s + 1) & 1) * 16384 + dir * 8192 + b * 512 + u] = h;
            if (s == 511) g_hT[b * 1024 + dir * 512 + u] = h;
        }
        xg0 = nx0; xg1 = nx1; xg2 = nx2; xg3 = nx3;

        if (s < 511) {
            __syncthreads();       // all h stores of this block complete
            if (tid == 0) {
                unsigned v;
                asm volatile("atom.add.release.gpu.global.u32 %0, [%1], 1;"
                             : "=r"(v) : "l"(myc) : "memory");
            }
            // per-warp wait: lane 0 polls both counters
            if (lane == 0) {
                const unsigned target = 64u * (unsigned)(s + 1);
                unsigned va, vb;
                while (true) {
                    asm volatile("ld.acquire.gpu.global.u32 %0, [%1];"
                                 : "=r"(va) : "l"(cA) : "memory");
                    asm volatile("ld.acquire.gpu.global.u32 %0, [%1];"
                                 : "=r"(vb) : "l"(cB) : "memory");
                    if (va + vb >= target) break;
                    __nanosleep(32);
                }
            }
            __syncwarp();
            // per-warp reload: this warp's own 64-k slice for all 16 batches
            const float4* src4 = (const float4*)(g_hbuf + ((s + 1) & 1) * 16384 + dir * 8192);
            const int k0f4 = k0 >> 2;
#pragma unroll
            for (int rep = 0; rep < 8; rep++) {
                int t = lane + rep * 32;          // 0..255
                int b = t >> 4, q = t & 15;
                float4 v4 = __ldcg(src4 + b * 128 + k0f4 + q);
                *(float4*)&h_s[b * 516 + k0 + q * 4] = v4;
            }
            __syncwarp();
        }
    }
}

// ---------------------------------------------------------------------------
// Attention chain
// ---------------------------------------------------------------------------
__global__ void build_Xatt_kernel()
{
    int i = blockIdx.x * blockDim.x + threadIdx.x;
    int m = i / 384, q = i % 384;
    int col = q * 4;
    int b = m >> 9;
    float4 v;
    if (col < 512)        v = *(const float4*)&g_hidden[b * 512 + col];
    else if (col < 1024)  v = *(const float4*)&g_encf[(size_t)m * 512 + (col - 512)];
    else                  v = *(const float4*)&g_encb[(size_t)m * 512 + (col - 1024)];
    *(float4*)&g_Xatt[(size_t)m * 1536 + col] = v;
}

__global__ void attdot_kernel(const int* __restrict__ doc, const float* __restrict__ v_w)
{
    int w = (blockIdx.x * blockDim.x + threadIdx.x) >> 5;
    int lane = threadIdx.x & 31;
    const float* e = g_energy + (size_t)w * 512;
    float s = 0.0f;
    for (int k = lane; k < 512; k += 32) s += e[k] * v_w[k];
#pragma unroll
    for (int o = 16; o > 0; o >>= 1) s += __shfl_xor_sync(0xFFFFFFFFu, s, o);
    if (lane == 0) g_att[w] = (doc[w] != 0) ? s : -1e10f;
}

__global__ void softmax_kernel()
{
    __shared__ float sred[512];
    int b = blockIdx.x, tid = threadIdx.x;
    float v = g_att[b * 512 + tid];
    sred[tid] = v; __syncthreads();
    for (int o = 256; o > 0; o >>= 1) { if (tid < o) sred[tid] = fmaxf(sred[tid], sred[tid + o]); __syncthreads(); }
    float mx = sred[0]; __syncthreads();
    float e = expf(v - mx);
    sred[tid] = e; __syncthreads();
    for (int o = 256; o > 0; o >>= 1) { if (tid < o) sred[tid] += sred[tid + o]; __syncthreads(); }
    g_a[b * 512 + tid] = e / sred[0];
}

__global__ void weighted_kernel()
{
    int i = blockIdx.x * blockDim.x + threadIdx.x;
    int b = i >> 10, e = i & 1023;
    const float* enc = (e < 512) ? (g_encf + (size_t)b * 512 * 512 + e)
                                 : (g_encb + (size_t)b * 512 * 512 + (e - 512));
    const float* ap = g_a + b * 512;
    float s = 0.0f;
    for (int l = 0; l < 512; l++) s += ap[l] * enc[(size_t)l * 512];
    g_weighted[i] = s;
}

// ---------------------------------------------------------------------------
// Decoder chain
// ---------------------------------------------------------------------------
__global__ void build_Xdec_kernel()
{
    int i = blockIdx.x * blockDim.x + threadIdx.x;
    int m = i / 384, q = i % 384;
    int col = q * 4;
    int b = m / 127;
    float4 v;
    if (col < 512) v = *(const float4*)&g_embs[(size_t)m * 512 + col];
    else           v = *(const float4*)&g_weighted[b * 1024 + (col - 512)];
    *(float4*)&g_Xdec[(size_t)m * 1536 + col] = v;
}

__global__ void dec_act_kernel()
{
    int i = blockIdx.x * blockDim.x + threadIdx.x;
    int m = i >> 9, u = i & 511;
    const float* gp = g_dg + (size_t)m * 2048;
    float gi = gp[u], gg = gp[1024 + u], go = gp[1536 + u];
    float c = sigf(gi) * tanhf(gg);
    g_dech[i] = sigf(go) * tanhf(c);
}

__global__ void build_Xpred_kernel()
{
    int i = blockIdx.x * blockDim.x + threadIdx.x;
    int m = i >> 9, q = i & 511;
    int col = q * 4;
    int b = m / 127;
    float4 v;
    if (col < 512)       v = *(const float4*)&g_dech[(size_t)m * 512 + col];
    else if (col < 1536) v = *(const float4*)&g_weighted[b * 1024 + (col - 512)];
    else                 v = *(const float4*)&g_embs[(size_t)m * 512 + (col - 1536)];
    *(float4*)&g_Xpred[(size_t)m * 2048 + col] = v;
}

// ---------------------------------------------------------------------------
// Loss
// ---------------------------------------------------------------------------
__global__ void loss_rows_kernel(const int* __restrict__ summ)
{
    __shared__ float sred[256];
    const int r = blockIdx.x;
    const int tid = threadIdx.x;
    const float* row = g_pred + (size_t)r * VV;
    float mx = -1e30f;
    for (int c = tid; c < VV; c += 256) mx = fmaxf(mx, row[c]);
    sred[tid] = mx; __syncthreads();
    for (int o = 128; o > 0; o >>= 1) { if (tid < o) sred[tid] = fmaxf(sred[tid], sred[tid + o]); __syncthreads(); }
    mx = sred[0]; __syncthreads();
    float sm = 0.0f;
    for (int c = tid; c < VV; c += 256) sm += expf(row[c] - mx);
    sred[tid] = sm; __syncthreads();
    for (int o = 128; o > 0; o >>= 1) { if (tid < o) sred[tid] += sred[tid + o]; __syncthreads(); }
    if (tid == 0) {
        int b = r / 127, t = r % 127;
        int tok = summ[b * TT + t + 1];
        g_nll[r] = logf(sred[0]) + mx - row[tok];
    }
}

__global__ void loss_final_kernel(float* __restrict__ out)
{
    __shared__ float sred[256];
    int tid = threadIdx.x;
    float s = 0.0f;
    for (int r = tid; r < 2032; r += 256) s += g_nll[r];
    sred[tid] = s; __syncthreads();
    for (int o = 128; o > 0; o >>= 1) { if (tid < o) sred[tid] += sred[tid + o]; __syncthreads(); }
    if (tid == 0)
        out[(size_t)BB * VV * TT] = (sred[0] + 16.0f * logf((float)VV)) / 2048.0f;
}

// ---------------------------------------------------------------------------
// Launch
// ---------------------------------------------------------------------------
extern "C" void kernel_launch(void* const* d_in, const int* in_sizes, int n_in,
                              void* d_out, int out_size)
{
    const int*   doc_ids = (const int*)  d_in[0];
    const int*   sum_ids = (const int*)  d_in[1];
    const float* E       = (const float*)d_in[2];
    const float* Wih_f   = (const float*)d_in[3];
    const float* Whh_f   = (const float*)d_in[4];
    const float* bih_f   = (const float*)d_in[5];
    const float* bhh_f   = (const float*)d_in[6];
    const float* Wih_b   = (const float*)d_in[7];
    const float* Whh_b   = (const float*)d_in[8];
    const float* bih_b   = (const float*)d_in[9];
    const float* bhh_b   = (const float*)d_in[10];
    const float* fc_W    = (const float*)d_in[11];
    const float* fc_b    = (const float*)d_in[12];
    const float* attn_W  = (const float*)d_in[13];
    const float* attn_b  = (const float*)d_in[14];
    const float* v_w     = (const float*)d_in[15];
    const float* dWih    = (const float*)d_in[16];
    const float* dbih    = (const float*)d_in[17];
    const float* dbhh    = (const float*)d_in[18];
    const float* dfc_W   = (const float*)d_in[19];
    const float* dfc_b   = (const float*)d_in[20];
    float* out = (float*)d_out;

    const int lstm_smem = (32 * 516 + 16 * 516 + 512 * 9 + 512 + 128) * 4;
    cudaFuncSetAttribute(lstm_kernel, cudaFuncAttributeMaxDynamicSharedMemorySize, lstm_smem);
    const int mma_smem = 55296;
    cudaFuncSetAttribute(gemm_mma_kernel, cudaFuncAttributeMaxDynamicSharedMemorySize, mma_smem);

    float *emb, *Wcat, *bcat, *xg, *hT, *hidden, *Xatt, *energy, *Xdec, *dbias, *dg, *Xpred, *pred;
    cudaGetSymbolAddress((void**)&emb,    g_emb);
    cudaGetSymbolAddress((void**)&Wcat,   g_Wcat);
    cudaGetSymbolAddress((void**)&bcat,   g_bcat);
    cudaGetSymbolAddress((void**)&xg,     g_xg);
    cudaGetSymbolAddress((void**)&hT,     g_hT);
    cudaGetSymbolAddress((void**)&hidden, g_hidden);
    cudaGetSymbolAddress((void**)&Xatt,   g_Xatt);
    cudaGetSymbolAddress((void**)&energy, g_energy);
    cudaGetSymbolAddress((void**)&Xdec,   g_Xdec);
    cudaGetSymbolAddress((void**)&dbias,  g_dbias);
    cudaGetSymbolAddress((void**)&dg,     g_dg);
    cudaGetSymbolAddress((void**)&Xpred,  g_Xpred);
    cudaGetSymbolAddress((void**)&pred,   g_pred);

    setup_kernel<<<2048, 256>>>(Wih_f, Wih_b, bih_f, bhh_f, bih_b, bhh_b, dbih, dbhh, out);
    embed_doc_kernel<<<4096, 256>>>(doc_ids, E);

    // xg = emb @ Wcat^T + bcat
    gemm_mma_kernel<<<dim3(64, 32), 256, mma_smem>>>(emb, Wcat, bcat, xg, 8192, 4096, 512, 0);

    // persistent bidirectional LSTM
    lstm_kernel<<<128, 256, lstm_smem>>>(Whh_f, Whh_b);

    // hidden = tanh(hT @ fc_W^T + fc_b)
    gemm_tn_kernel<<<dim3(4, 1), 256>>>(hT, fc_W, fc_b, hidden, 16, 512, 1024, 1);

    // attention
    build_Xatt_kernel<<<12288, 256>>>();
    gemm_mma_kernel<<<dim3(64, 4), 256, mma_smem>>>(Xatt, attn_W, attn_b, energy, 8192, 512, 1536, 1);
    attdot_kernel<<<1024, 256>>>(doc_ids, v_w);
    softmax_kernel<<<16, 512>>>();
    weighted_kernel<<<64, 256>>>();

    // decoder
    embed_sum_kernel<<<1016, 256>>>(sum_ids, E);
    build_Xdec_kernel<<<3048, 256>>>();
    gemm_mma_kernel<<<dim3(16, 16), 256, mma_smem>>>(Xdec, dWih, dbias, dg, 2032, 2048, 1536, 0);
    dec_act_kernel<<<4064, 256>>>();
    build_Xpred_kernel<<<4064, 256>>>();

    // pred GEMM -> row-major g_pred, then coalesced transpose into out
    gemm_mma_kernel<<<dim3(16, 166), 256, mma_smem>>>(Xpred, dfc_W, dfc_b, pred, 2032, VV, 2048, 0);
    transpose_out_kernel<<<dim3(661, 4, 16), dim3(32, 8)>>>(out);

    // loss
    loss_rows_kernel<<<2032, 256>>>(sum_ids);
    loss_final_kernel<<<1, 256>>>(out);
}

// round 16
// speedup vs baseline: 1.0079x; 1.0079x over previous
#include <cuda_runtime.h>
#include <cuda_bf16.h>
#include <cuda_fp16.h>
#include <cstdint>
#include <math.h>

#define BB 16
#define LL 512
#define TT 128
#define VV 21128
#define DD 512

// packed fp32x2 helpers (scalar gemm + lstm)
#define PACK2(d, a, b)  asm("mov.b64 %0, {%1,%2};" : "=l"(d) : "f"(a), "f"(b))
#define FMA2(acc, a, b) asm("fma.rn.f32x2 %0, %1, %2, %3;" : "=l"(acc) : "l"(a), "l"(b), "l"(acc))
#define UNPACK2(lo, hi, p) asm("mov.b64 {%0,%1}, %2;" : "=f"(lo), "=f"(hi) : "l"(p))

// ---------------------------------------------------------------------------
// Device scratch
// ---------------------------------------------------------------------------
__device__ __align__(16) float g_emb[BB * LL * DD];
__device__ __align__(16) float g_Wcat[4096 * 512];
__device__ __align__(16) float g_bcat[4096];
__device__ __align__(16) float g_xg[8192 * 4096];
__device__ __align__(16) float g_encf[BB * LL * DD];
__device__ __align__(16) float g_encb[BB * LL * DD];
__device__ __align__(16) float g_hbuf[2 * 2 * BB * DD];
__device__ __align__(16) float g_hT[BB * 1024];
__device__ __align__(16) float g_hidden[BB * DD];
__device__ __align__(16) float g_Xatt[8192 * 1536];
__device__ __align__(16) float g_energy[8192 * 512];
__device__ __align__(16) float g_att[8192];
__device__ __align__(16) float g_a[8192];
__device__ __align__(16) float g_weighted[BB * 1024];
__device__ __align__(16) float g_embs[2032 * 512];
__device__ __align__(16) float g_Xdec[2032 * 1536];
__device__ __align__(16) float g_dbias[2048];
__device__ __align__(16) float g_dg[2032 * 2048];
__device__ __align__(16) float g_dech[2032 * 512];
__device__ __align__(16) float g_Xpred[2032 * 2048];
__device__ __align__(16) float g_pred[2032 * VV];
__device__ float g_nll[2032];
// per-block step flags, 128B stride each: flag[i] at g_flags[i*32]
__device__ __align__(128) unsigned g_flags[2 * 64 * 32];

__device__ __forceinline__ float sigf(float x) { return 1.0f / (1.0f + expf(-x)); }

__device__ __forceinline__ unsigned smem_u32(const void* p)
{
    unsigned a;
    asm("{ .reg .u64 t; cvta.to.shared.u64 t, %1; cvt.u32.u64 %0, t; }" : "=r"(a) : "l"(p));
    return a;
}

#define LDSM_X4(r0, r1, r2, r3, addr) \
    asm volatile("ldmatrix.sync.aligned.m8n8.x4.shared.b16 {%0,%1,%2,%3}, [%4];" \
                 : "=r"(r0), "=r"(r1), "=r"(r2), "=r"(r3) : "r"(addr))

#define MMA_F16(c, a, b) \
    asm volatile("mma.sync.aligned.m16n8k16.row.col.f32.f16.f16.f32 " \
                 "{%0,%1,%2,%3}, {%4,%5,%6,%7}, {%8,%9}, {%0,%1,%2,%3};" \
                 : "+f"((c)[0]), "+f"((c)[1]), "+f"((c)[2]), "+f"((c)[3]) \
                 : "r"((a)[0]), "r"((a)[1]), "r"((a)[2]), "r"((a)[3]), \
                   "r"((b)[0]), "r"((b)[1]))

// split fp32x4 -> fp16x4 hi (uint2) + fp16x4 lo (uint2)   [A operand]
__device__ __forceinline__ void split4h(const float4& v, uint2& h, uint2& l)
{
    __half2 h01 = __floats2half2_rn(v.x, v.y);
    __half2 h23 = __floats2half2_rn(v.z, v.w);
    float2 f01 = __half22float2(h01);
    float2 f23 = __half22float2(h23);
    __half2 l01 = __floats2half2_rn(v.x - f01.x, v.y - f01.y);
    __half2 l23 = __floats2half2_rn(v.z - f23.x, v.w - f23.y);
    h = make_uint2(*(unsigned*)&h01, *(unsigned*)&h23);
    l = make_uint2(*(unsigned*)&l01, *(unsigned*)&l23);
}

// fp32x4 -> fp16x4 hi only   [B operand]
__device__ __forceinline__ uint2 cvt4h(const float4& v)
{
    __half2 h01 = __floats2half2_rn(v.x, v.y);
    __half2 h23 = __floats2half2_rn(v.z, v.w);
    return make_uint2(*(unsigned*)&h01, *(unsigned*)&h23);
}

// ---------------------------------------------------------------------------
// fp16 split-precision warp-mma GEMM (2 passes):
//   C[M,N] = (A_hi + A_lo)[M,K] @ B_hi[N,K]^T + bias
//   mode 0: plain   1: tanh
// ---------------------------------------------------------------------------
__global__ void __launch_bounds__(256, 1)
gemm_mma_kernel(const float* __restrict__ A, const float* __restrict__ Bw,
                const float* __restrict__ bias, float* __restrict__ C,
                int M, int N, int K, int mode)
{
    extern __shared__ __align__(16) char smem[];
    const unsigned sbase = smem_u32(smem);
    const unsigned OFF_AH = 0, OFF_AL = 18432, OFF_BH = 36864;

    const int tid  = threadIdx.x;
    const int wid  = tid >> 5;
    const int lane = tid & 31;
    const int wm   = wid >> 2;
    const int wn   = wid & 3;
    const int row0 = blockIdx.x * 128;
    const int col0 = blockIdx.y * 128;

    float acc[4][4][4];
#pragma unroll
    for (int i = 0; i < 4; i++)
#pragma unroll
        for (int j = 0; j < 4; j++)
#pragma unroll
            for (int q = 0; q < 4; q++) acc[i][j][q] = 0.0f;

    const int a_lr = lane & 15, a_lh = lane >> 4;
    const int b_g = lane >> 3, b_l8 = lane & 7;
    const int b_rofs = (b_g >> 1) * 8 + b_l8;
    const int b_cofs = (b_g & 1) * 8;

    int srow[8], scol[8];
#pragma unroll
    for (int i = 0; i < 8; i++) {
        int idx = tid + (i << 8);
        srow[i] = idx >> 4;
        scol[i] = (idx & 15) << 2;
    }

    const float4 zf = make_float4(0.f, 0.f, 0.f, 0.f);
    float4 pa[8], pb[8];
#pragma unroll
    for (int i = 0; i < 8; i++) {
        int ar = row0 + srow[i];
        pa[i] = (ar < M) ? *(const float4*)(A + (size_t)ar * K + scol[i]) : zf;
        int br = col0 + srow[i];
        pb[i] = (br < N) ? *(const float4*)(Bw + (size_t)br * K + scol[i]) : zf;
    }

    const int nch = K >> 6;
    for (int kc = 0; kc < nch; kc++) {
        __syncthreads();
#pragma unroll
        for (int i = 0; i < 8; i++) {
            unsigned so = srow[i] * 144 + scol[i] * 2;
            uint2 h, l;
            split4h(pa[i], h, l);
            *(uint2*)(smem + OFF_AH + so) = h;
            *(uint2*)(smem + OFF_AL + so) = l;
            *(uint2*)(smem + OFF_BH + so) = cvt4h(pb[i]);
        }
        __syncthreads();

        if (kc + 1 < nch) {
            const int k0 = (kc + 1) << 6;
#pragma unroll
            for (int i = 0; i < 8; i++) {
                int ar = row0 + srow[i];
                pa[i] = (ar < M) ? *(const float4*)(A + (size_t)ar * K + k0 + scol[i]) : zf;
                int br = col0 + srow[i];
                pb[i] = (br < N) ? *(const float4*)(Bw + (size_t)br * K + k0 + scol[i]) : zf;
            }
        }

#pragma unroll
        for (int k16 = 0; k16 < 4; k16++) {
            const int kb = k16 << 4;
            unsigned aH[4][4], aL[4][4], bH[4][2];
#pragma unroll
            for (int i = 0; i < 4; i++) {
                unsigned rm = (unsigned)(wm * 64 + i * 16 + a_lr);
                unsigned off = rm * 144 + (unsigned)(kb + a_lh * 8) * 2;
                LDSM_X4(aH[i][0], aH[i][1], aH[i][2], aH[i][3], sbase + OFF_AH + off);
                LDSM_X4(aL[i][0], aL[i][1], aL[i][2], aL[i][3], sbase + OFF_AL + off);
            }
#pragma unroll
            for (int j2 = 0; j2 < 2; j2++) {
                unsigned rn = (unsigned)(wn * 32 + j2 * 16 + b_rofs);
                unsigned off = rn * 144 + (unsigned)(kb + b_cofs) * 2;
                LDSM_X4(bH[2 * j2][0], bH[2 * j2][1], bH[2 * j2 + 1][0], bH[2 * j2 + 1][1],
                        sbase + OFF_BH + off);
            }
#pragma unroll
            for (int i = 0; i < 4; i++)
#pragma unroll
                for (int j = 0; j < 4; j++) {
                    MMA_F16(acc[i][j], aH[i], bH[j]);
                    MMA_F16(acc[i][j], aL[i], bH[j]);
                }
        }
    }

    const int lm = lane >> 2;
    const int ln = (lane & 3) * 2;
#pragma unroll
    for (int i = 0; i < 4; i++) {
#pragma unroll
        for (int j = 0; j < 4; j++) {
            int nbase = col0 + wn * 32 + j * 8 + ln;
#pragma unroll
            for (int half = 0; half < 2; half++) {
                int r = row0 + wm * 64 + i * 16 + lm + half * 8;
                if (r >= M) continue;
                float v0 = acc[i][j][half * 2 + 0];
                float v1 = acc[i][j][half * 2 + 1];
                if (nbase < N) {
                    float v = v0 + __ldg(&bias[nbase]);
                    C[(size_t)r * N + nbase] = (mode == 1) ? tanhf(v) : v;
                }
                if (nbase + 1 < N) {
                    float v = v1 + __ldg(&bias[nbase + 1]);
                    C[(size_t)r * N + nbase + 1] = (mode == 1) ? tanhf(v) : v;
                }
            }
        }
    }
}

// ---------------------------------------------------------------------------
// Transpose g_pred[r= b*127+t-1][v] -> out[b][v][t]
// ---------------------------------------------------------------------------
__global__ void transpose_out_kernel(float* __restrict__ out)
{
    __shared__ float tile[32][33];
    const int b  = blockIdx.z;
    const int v0 = blockIdx.x * 32;
    const int t0 = 1 + blockIdx.y * 32;
    const int tv = threadIdx.x;
    const int tr = threadIdx.y;
#pragma unroll
    for (int i = 0; i < 4; i++) {
        int t = t0 + tr * 4 + i;
        int v = v0 + tv;
        if (t < 128 && v < VV)
            tile[tr * 4 + i][tv] = g_pred[(size_t)(b * 127 + t - 1) * VV + v];
    }
    __syncthreads();
#pragma unroll
    for (int i = 0; i < 4; i++) {
        int v = v0 + tr * 4 + i;
        int t = t0 + tv;
        if (t < 128 && v < VV)
            out[((size_t)b * VV + v) * TT + t] = tile[tv][tr * 4 + i];
    }
}

// ---------------------------------------------------------------------------
// Setup
// ---------------------------------------------------------------------------
__global__ void setup_kernel(const float* __restrict__ Wih_f, const float* __restrict__ Wih_b,
                             const float* __restrict__ bih_f, const float* __restrict__ bhh_f,
                             const float* __restrict__ bih_b, const float* __restrict__ bhh_b,
                             const float* __restrict__ dbih, const float* __restrict__ dbhh,
                             float* __restrict__ out)
{
    int i = blockIdx.x * blockDim.x + threadIdx.x;
    {
        int n  = i >> 7;
        int k4 = (i & 127) << 2;
        const float* W = (n < 2048) ? Wih_f : Wih_b;
        *(float4*)&g_Wcat[(size_t)n * 512 + k4] =
            *(const float4*)&W[(size_t)(n & 2047) * 512 + k4];
    }
    if (i < 4096)
        g_bcat[i] = (i < 2048) ? (bih_f[i] + bhh_f[i]) : (bih_b[i - 2048] + bhh_b[i - 2048]);
    if (i < 2048)
        g_dbias[i] = dbih[i] + dbhh[i];
    if (i < BB * VV)
        out[(size_t)i * TT] = 0.0f;
    if (i < 2 * 64 * 32) g_flags[i] = 0u;
}

// ---------------------------------------------------------------------------
// Embedding gathers
// ---------------------------------------------------------------------------
__global__ void embed_doc_kernel(const int* __restrict__ ids, const float* __restrict__ E)
{
    int i = blockIdx.x * blockDim.x + threadIdx.x;
    int m = i >> 7, d4 = (i & 127) << 2;
    int id = ids[m];
    *(float4*)&g_emb[(size_t)m * 512 + d4] = *(const float4*)&E[(size_t)id * 512 + d4];
}

__global__ void embed_sum_kernel(const int* __restrict__ summ, const float* __restrict__ E)
{
    int i = blockIdx.x * blockDim.x + threadIdx.x;
    int m = i >> 7, d4 = (i & 127) << 2;
    int b = m / 127, t = m % 127;
    int id = summ[b * TT + t];
    *(float4*)&g_embs[(size_t)m * 512 + d4] = *(const float4*)&E[(size_t)id * 512 + d4];
}

// ---------------------------------------------------------------------------
// Small scalar GEMM (f32x2) for the 16-row 'hidden' layer
// ---------------------------------------------------------------------------
__global__ void __launch_bounds__(256)
gemm_tn_kernel(const float* __restrict__ A, const float* __restrict__ Bw,
               const float* __restrict__ bias, float* __restrict__ C,
               int M, int N, int K, int mode)
{
    __shared__ __align__(16) float As[2][8 * 132];
    __shared__ __align__(16) float Bs[2][8 * 132];
    const int tid = threadIdx.x;
    const int row0 = blockIdx.y * 128;
    const int col0 = blockIdx.x * 128;
    const int lr = tid >> 1;
    const int lk = (tid & 1) * 4;
    const int ty = tid >> 4, tx = tid & 15;

    unsigned long long acc2[8][4];
#pragma unroll
    for (int i = 0; i < 8; i++)
#pragma unroll
        for (int j = 0; j < 4; j++) acc2[i][j] = 0ULL;

    const int arow = row0 + lr;
    const int brow = col0 + lr;
    const bool aval = arow < M;
    const bool bval = brow < N;
    const float* Aptr = A + (size_t)arow * K + lk;
    const float* Bptr = Bw + (size_t)brow * K + lk;
    const int NT = K >> 3;

    float4 a4 = aval ? *(const float4*)Aptr : make_float4(0.f, 0.f, 0.f, 0.f);
    float4 b4 = bval ? *(const float4*)Bptr : make_float4(0.f, 0.f, 0.f, 0.f);
    As[0][(lk + 0) * 132 + lr] = a4.x; As[0][(lk + 1) * 132 + lr] = a4.y;
    As[0][(lk + 2) * 132 + lr] = a4.z; As[0][(lk + 3) * 132 + lr] = a4.w;
    Bs[0][(lk + 0) * 132 + lr] = b4.x; Bs[0][(lk + 1) * 132 + lr] = b4.y;
    Bs[0][(lk + 2) * 132 + lr] = b4.z; Bs[0][(lk + 3) * 132 + lr] = b4.w;
    __syncthreads();

    for (int t = 0; t < NT; t++) {
        const int cur = t & 1;
        if (t + 1 < NT) {
            a4 = aval ? *(const float4*)(Aptr + (size_t)(t + 1) * 8) : make_float4(0.f, 0.f, 0.f, 0.f);
            b4 = bval ? *(const float4*)(Bptr + (size_t)(t + 1) * 8) : make_float4(0.f, 0.f, 0.f, 0.f);
        }
#pragma unroll
        for (int k = 0; k < 8; k++) {
            float4 x0 = *(const float4*)&As[cur][k * 132 + ty * 8];
            float4 x1 = *(const float4*)&As[cur][k * 132 + ty * 8 + 4];
            float4 y0 = *(const float4*)&Bs[cur][k * 132 + tx * 8];
            float4 y1 = *(const float4*)&Bs[cur][k * 132 + tx * 8 + 4];
            unsigned long long rbp[4];
            PACK2(rbp[0], y0.x, y0.y);
            PACK2(rbp[1], y0.z, y0.w);
            PACK2(rbp[2], y1.x, y1.y);
            PACK2(rbp[3], y1.z, y1.w);
            float ra[8] = {x0.x, x0.y, x0.z, x0.w, x1.x, x1.y, x1.z, x1.w};
#pragma unroll
            for (int i = 0; i < 8; i++) {
                unsigned long long rad;
                PACK2(rad, ra[i], ra[i]);
                FMA2(acc2[i][0], rad, rbp[0]);
                FMA2(acc2[i][1], rad, rbp[1]);
                FMA2(acc2[i][2], rad, rbp[2]);
                FMA2(acc2[i][3], rad, rbp[3]);
            }
        }
        if (t + 1 < NT) {
            const int nxt = cur ^ 1;
            As[nxt][(lk + 0) * 132 + lr] = a4.x; As[nxt][(lk + 1) * 132 + lr] = a4.y;
            As[nxt][(lk + 2) * 132 + lr] = a4.z; As[nxt][(lk + 3) * 132 + lr] = a4.w;
            Bs[nxt][(lk + 0) * 132 + lr] = b4.x; Bs[nxt][(lk + 1) * 132 + lr] = b4.y;
            Bs[nxt][(lk + 2) * 132 + lr] = b4.z; Bs[nxt][(lk + 3) * 132 + lr] = b4.w;
            __syncthreads();
        }
    }

#pragma unroll
    for (int i = 0; i < 8; i++) {
        int r = row0 + ty * 8 + i;
        if (r >= M) continue;
#pragma unroll
        for (int jj = 0; jj < 4; jj++) {
            float lo, hi;
            UNPACK2(lo, hi, acc2[i][jj]);
            float vv[2] = {lo, hi};
#pragma unroll
            for (int q = 0; q < 2; q++) {
                int c = col0 + tx * 8 + jj * 2 + q;
                if (c >= N) continue;
                float v = vv[q] + bias[c];
                C[(size_t)r * N + c] = (mode == 1) ? tanhf(v) : v;
            }
        }
    }
}

// ---------------------------------------------------------------------------
// Persistent bidirectional LSTM; 128B-strided per-block flag barrier
// ---------------------------------------------------------------------------
__global__ void __launch_bounds__(256)
lstm_kernel(const float* __restrict__ Whh_f, const float* __restrict__ Whh_b)
{
    extern __shared__ __align__(16) float sm[];
    float* Whh_s  = sm;                        // 32 x 516
    float* h_s    = sm + 32 * 516;             // 16 x 516
    float* red    = h_s + 16 * 516;            // 512 * 9
    float* gate_s = red + 512 * 9;             // 32 x 16
    float* c_s    = gate_s + 512;              // 128

    const int tid = threadIdx.x;
    const int blk = blockIdx.x;
    const int dir = blk >> 6;
    const int u0  = (blk & 63) * 8;
    const float* Whh = dir ? Whh_b : Whh_f;

    for (int idx = tid; idx < 32 * 512; idx += 256) {
        int lrow = idx >> 9, k = idx & 511;
        int gt = lrow >> 3, j = lrow & 7;
        Whh_s[lrow * 516 + k] = Whh[(size_t)(gt * 512 + u0 + j) * 512 + k];
    }
    for (int idx = tid; idx < 16 * 516; idx += 256) h_s[idx] = 0.0f;
    if (tid < 128) c_s[tid] = 0.0f;
    __syncthreads();

    const int ks  = tid >> 5;
    const int til = tid & 31;
    const int rt4 = (til >> 2) * 4;
    const int bt4 = (til & 3) * 4;
    unsigned* myflag   = &g_flags[(dir * 64 + (blk & 63)) * 32];
    unsigned* dirflags = &g_flags[dir * 64 * 32];

    for (int s = 0; s < 512; s++) {
        const int pos = dir ? (511 - s) : s;

        unsigned long long acc2[4][2];
#pragma unroll
        for (int j = 0; j < 4; j++) { acc2[j][0] = 0ULL; acc2[j][1] = 0ULL; }

        const int k0 = ks * 64;
#pragma unroll 4
        for (int kk = 0; kk < 64; kk += 4) {
            const int k = k0 + kk;
            float4 w0 = *(const float4*)&Whh_s[(rt4 + 0) * 516 + k];
            float4 w1 = *(const float4*)&Whh_s[(rt4 + 1) * 516 + k];
            float4 w2 = *(const float4*)&Whh_s[(rt4 + 2) * 516 + k];
            float4 w3 = *(const float4*)&Whh_s[(rt4 + 3) * 516 + k];
            float4 h0 = *(const float4*)&h_s[(bt4 + 0) * 516 + k];
            float4 h1 = *(const float4*)&h_s[(bt4 + 1) * 516 + k];
            float4 h2 = *(const float4*)&h_s[(bt4 + 2) * 516 + k];
            float4 h3 = *(const float4*)&h_s[(bt4 + 3) * 516 + k];
#define LSTM_STEPK(CC)                                                        \
            {                                                                 \
                unsigned long long hp0, hp1, wd;                              \
                PACK2(hp0, h0.CC, h1.CC);                                     \
                PACK2(hp1, h2.CC, h3.CC);                                     \
                PACK2(wd, w0.CC, w0.CC);                                      \
                FMA2(acc2[0][0], wd, hp0); FMA2(acc2[0][1], wd, hp1);         \
                PACK2(wd, w1.CC, w1.CC);                                      \
                FMA2(acc2[1][0], wd, hp0); FMA2(acc2[1][1], wd, hp1);         \
                PACK2(wd, w2.CC, w2.CC);                                      \
                FMA2(acc2[2][0], wd, hp0); FMA2(acc2[2][1], wd, hp1);         \
                PACK2(wd, w3.CC, w3.CC);                                      \
                FMA2(acc2[3][0], wd, hp0); FMA2(acc2[3][1], wd, hp1);         \
            }
            LSTM_STEPK(x)
            LSTM_STEPK(y)
            LSTM_STEPK(z)
            LSTM_STEPK(w)
#undef LSTM_STEPK
        }
#pragma unroll
        for (int j = 0; j < 4; j++)
#pragma unroll
            for (int p = 0; p < 2; p++) {
                float lo, hi;
                UNPACK2(lo, hi, acc2[j][p]);
                red[((rt4 + j) * 16 + bt4 + 2 * p + 0) * 9 + ks] = lo;
                red[((rt4 + j) * 16 + bt4 + 2 * p + 1) * 9 + ks] = hi;
            }
        __syncthreads();

#pragma unroll
        for (int rep = 0; rep < 2; rep++) {
            int p = tid + rep * 256;
            float ssum = 0.0f;
#pragma unroll
            for (int q = 0; q < 8; q++) ssum += red[p * 9 + q];
            gate_s[p] = ssum;
        }
        __syncthreads();

        if (tid < 128) {
            const int j = tid & 7, b = tid >> 3;
            const size_t xrow = (size_t)(b * 512 + pos) * 4096 + dir * 2048 + u0 + j;
            float gi = gate_s[(0 * 8 + j) * 16 + b] + g_xg[xrow];
            float gf = gate_s[(1 * 8 + j) * 16 + b] + g_xg[xrow + 512];
            float gg = gate_s[(2 * 8 + j) * 16 + b] + g_xg[xrow + 1024];
            float go = gate_s[(3 * 8 + j) * 16 + b] + g_xg[xrow + 1536];
            float c = sigf(gf) * c_s[tid] + sigf(gi) * tanhf(gg);
            c_s[tid] = c;
            float h = sigf(go) * tanhf(c);
            const int u = u0 + j;
            (dir ? g_encb : g_encf)[(size_t)(b * 512 + pos) * 512 + u] = h;
            g_hbuf[((s + 1) & 1) * 16384 + dir * 8192 + b * 512 + u] = h;
            if (s == 511) g_hT[b * 1024 + dir * 512 + u] = h;
        }

        if (s < 511) {
            __syncthreads();      // all h writes of this block done
            if (tid == 0) {
                // release-store own 128B-strided flag: parallel arrivals
                asm volatile("st.release.gpu.global.u32 [%0], %1;"
                             :: "l"(myflag), "r"((unsigned)(s + 1)) : "memory");
            }
            if (tid < 64) {
                // each thread polls one distinct 128B line
                unsigned v;
                do {
                    asm volatile("ld.acquire.gpu.global.u32 %0, [%1];"
                                 : "=r"(v) : "l"(dirflags + tid * 32) : "memory");
                    if (v >= (unsigned)(s + 1)) break;
                    __nanosleep(32);
                } while (true);
            }
            __syncthreads();
            const float4* src4 = (const float4*)(g_hbuf + ((s + 1) & 1) * 16384 + dir * 8192);
            for (int idx = tid; idx < 2048; idx += 256) {
                float4 v4 = __ldcg(src4 + idx);
                int row = idx >> 7;
                int k4  = (idx & 127) << 2;
                *(float4*)&h_s[row * 516 + k4] = v4;
            }
            __syncthreads();
        }
    }
}

// ---------------------------------------------------------------------------
// Attention chain
// ---------------------------------------------------------------------------
__global__ void build_Xatt_kernel()
{
    int i = blockIdx.x * blockDim.x + threadIdx.x;
    int m = i / 384, q = i % 384;
    int col = q * 4;
    int b = m >> 9;
    float4 v;
    if (col < 512)        v = *(const float4*)&g_hidden[b * 512 + col];
    else if (col < 1024)  v = *(const float4*)&g_encf[(size_t)m * 512 + (col - 512)];
    else                  v = *(const float4*)&g_encb[(size_t)m * 512 + (col - 1024)];
    *(float4*)&g_Xatt[(size_t)m * 1536 + col] = v;
}

__global__ void attdot_kernel(const int* __restrict__ doc, const float* __restrict__ v_w)
{
    int w = (blockIdx.x * blockDim.x + threadIdx.x) >> 5;
    int lane = threadIdx.x & 31;
    const float* e = g_energy + (size_t)w * 512;
    float s = 0.0f;
    for (int k = lane; k < 512; k += 32) s += e[k] * v_w[k];
#pragma unroll
    for (int o = 16; o > 0; o >>= 1) s += __shfl_xor_sync(0xFFFFFFFFu, s, o);
    if (lane == 0) g_att[w] = (doc[w] != 0) ? s : -1e10f;
}

__global__ void softmax_kernel()
{
    __shared__ float sred[512];
    int b = blockIdx.x, tid = threadIdx.x;
    float v = g_att[b * 512 + tid];
    sred[tid] = v; __syncthreads();
    for (int o = 256; o > 0; o >>= 1) { if (tid < o) sred[tid] = fmaxf(sred[tid], sred[tid + o]); __syncthreads(); }
    float mx = sred[0]; __syncthreads();
    float e = expf(v - mx);
    sred[tid] = e; __syncthreads();
    for (int o = 256; o > 0; o >>= 1) { if (tid < o) sred[tid] += sred[tid + o]; __syncthreads(); }
    g_a[b * 512 + tid] = e / sred[0];
}

__global__ void weighted_kernel()
{
    int i = blockIdx.x * blockDim.x + threadIdx.x;
    int b = i >> 10, e = i & 1023;
    const float* enc = (e < 512) ? (g_encf + (size_t)b * 512 * 512 + e)
                                 : (g_encb + (size_t)b * 512 * 512 + (e - 512));
    const float* ap = g_a + b * 512;
    float s = 0.0f;
    for (int l = 0; l < 512; l++) s += ap[l] * enc[(size_t)l * 512];
    g_weighted[i] = s;
}

// ---------------------------------------------------------------------------
// Decoder chain
// ---------------------------------------------------------------------------
__global__ void build_Xdec_kernel()
{
    int i = blockIdx.x * blockDim.x + threadIdx.x;
    int m = i / 384, q = i % 384;
    int col = q * 4;
    int b = m / 127;
    float4 v;
    if (col < 512) v = *(const float4*)&g_embs[(size_t)m * 512 + col];
    else           v = *(const float4*)&g_weighted[b * 1024 + (col - 512)];
    *(float4*)&g_Xdec[(size_t)m * 1536 + col] = v;
}

__global__ void dec_act_kernel()
{
    int i = blockIdx.x * blockDim.x + threadIdx.x;
    int m = i >> 9, u = i & 511;
    const float* gp = g_dg + (size_t)m * 2048;
    float gi = gp[u], gg = gp[1024 + u], go = gp[1536 + u];
    float c = sigf(gi) * tanhf(gg);
    g_dech[i] = sigf(go) * tanhf(c);
}

__global__ void build_Xpred_kernel()
{
    int i = blockIdx.x * blockDim.x + threadIdx.x;
    int m = i >> 9, q = i & 511;
    int col = q * 4;
    int b = m / 127;
    float4 v;
    if (col < 512)       v = *(const float4*)&g_dech[(size_t)m * 512 + col];
    else if (col < 1536) v = *(const float4*)&g_weighted[b * 1024 + (col - 512)];
    else                 v = *(const float4*)&g_embs[(size_t)m * 512 + (col - 1536)];
    *(float4*)&g_Xpred[(size_t)m * 2048 + col] = v;
}

// ---------------------------------------------------------------------------
// Loss
// ---------------------------------------------------------------------------
__global__ void loss_rows_kernel(const int* __restrict__ summ)
{
    __shared__ float sred[256];
    const int r = blockIdx.x;
    const int tid = threadIdx.x;
    const float* row = g_pred + (size_t)r * VV;
    float mx = -1e30f;
    for (int c = tid; c < VV; c += 256) mx = fmaxf(mx, row[c]);
    sred[tid] = mx; __syncthreads();
    for (int o = 128; o > 0; o >>= 1) { if (tid < o) sred[tid] = fmaxf(sred[tid], sred[tid + o]); __syncthreads(); }
    mx = sred[0]; __syncthreads();
    float sm = 0.0f;
    for (int c = tid; c < VV; c += 256) sm += expf(row[c] - mx);
    sred[tid] = sm; __syncthreads();
    for (int o = 128; o > 0; o >>= 1) { if (tid < o) sred[tid] += sred[tid + o]; __syncthreads(); }
    if (tid == 0) {
        int b = r / 127, t = r % 127;
        int tok = summ[b * TT + t + 1];
        g_nll[r] = logf(sred[0]) + mx - row[tok];
    }
}

__global__ void loss_final_kernel(float* __restrict__ out)
{
    __shared__ float sred[256];
    int tid = threadIdx.x;
    float s = 0.0f;
    for (int r = tid; r < 2032; r += 256) s += g_nll[r];
    sred[tid] = s; __syncthreads();
    for (int o = 128; o > 0; o >>= 1) { if (tid < o) sred[tid] += sred[tid + o]; __syncthreads(); }
    if (tid == 0)
        out[(size_t)BB * VV * TT] = (sred[0] + 16.0f * logf((float)VV)) / 2048.0f;
}

// ---------------------------------------------------------------------------
// Launch
// ---------------------------------------------------------------------------
extern "C" void kernel_launch(void* const* d_in, const int* in_sizes, int n_in,
                              void* d_out, int out_size)
{
    const int*   doc_ids = (const int*)  d_in[0];
    const int*   sum_ids = (const int*)  d_in[1];
    const float* E       = (const float*)d_in[2];
    const float* Wih_f   = (const float*)d_in[3];
    const float* Whh_f   = (const float*)d_in[4];
    const float* bih_f   = (const float*)d_in[5];
    const float* bhh_f   = (const float*)d_in[6];
    const float* Wih_b   = (const float*)d_in[7];
    const float* Whh_b   = (const float*)d_in[8];
    const float* bih_b   = (const float*)d_in[9];
    const float* bhh_b   = (const float*)d_in[10];
    const float* fc_W    = (const float*)d_in[11];
    const float* fc_b    = (const float*)d_in[12];
    const float* attn_W  = (const float*)d_in[13];
    const float* attn_b  = (const float*)d_in[14];
    const float* v_w     = (const float*)d_in[15];
    const float* dWih    = (const float*)d_in[16];
    const float* dbih    = (const float*)d_in[17];
    const float* dbhh    = (const float*)d_in[18];
    const float* dfc_W   = (const float*)d_in[19];
    const float* dfc_b   = (const float*)d_in[20];
    float* out = (float*)d_out;

    const int lstm_smem = (32 * 516 + 16 * 516 + 512 * 9 + 512 + 128) * 4;
    cudaFuncSetAttribute(lstm_kernel, cudaFuncAttributeMaxDynamicSharedMemorySize, lstm_smem);
    const int mma_smem = 55296;
    cudaFuncSetAttribute(gemm_mma_kernel, cudaFuncAttributeMaxDynamicSharedMemorySize, mma_smem);

    float *emb, *Wcat, *bcat, *xg, *hT, *hidden, *Xatt, *energy, *Xdec, *dbias, *dg, *Xpred, *pred;
    cudaGetSymbolAddress((void**)&emb,    g_emb);
    cudaGetSymbolAddress((void**)&Wcat,   g_Wcat);
    cudaGetSymbolAddress((void**)&bcat,   g_bcat);
    cudaGetSymbolAddress((void**)&xg,     g_xg);
    cudaGetSymbolAddress((void**)&hT,     g_hT);
    cudaGetSymbolAddress((void**)&hidden, g_hidden);
    cudaGetSymbolAddress((void**)&Xatt,   g_Xatt);
    cudaGetSymbolAddress((void**)&energy, g_energy);
    cudaGetSymbolAddress((void**)&Xdec,   g_Xdec);
    cudaGetSymbolAddress((void**)&dbias,  g_dbias);
    cudaGetSymbolAddress((void**)&dg,     g_dg);
    cudaGetSymbolAddress((void**)&Xpred,  g_Xpred);
    cudaGetSymbolAddress((void**)&pred,   g_pred);

    setup_kernel<<<2048, 256>>>(Wih_f, Wih_b, bih_f, bhh_f, bih_b, bhh_b, dbih, dbhh, out);
    embed_doc_kernel<<<4096, 256>>>(doc_ids, E);

    // xg = emb @ Wcat^T + bcat
    gemm_mma_kernel<<<dim3(64, 32), 256, mma_smem>>>(emb, Wcat, bcat, xg, 8192, 4096, 512, 0);

    // persistent bidirectional LSTM
    lstm_kernel<<<128, 256, lstm_smem>>>(Whh_f, Whh_b);

    // hidden = tanh(hT @ fc_W^T + fc_b)
    gemm_tn_kernel<<<dim3(4, 1), 256>>>(hT, fc_W, fc_b, hidden, 16, 512, 1024, 1);

    // attention
    build_Xatt_kernel<<<12288, 256>>>();
    gemm_mma_kernel<<<dim3(64, 4), 256, mma_smem>>>(Xatt, attn_W, attn_b, energy, 8192, 512, 1536, 1);
    attdot_kernel<<<1024, 256>>>(doc_ids, v_w);
    softmax_kernel<<<16, 512>>>();
    weighted_kernel<<<64, 256>>>();

    // decoder
    embed_sum_kernel<<<1016, 256>>>(sum_ids, E);
    build_Xdec_kernel<<<3048, 256>>>();
    gemm_mma_kernel<<<dim3(16, 16), 256, mma_smem>>>(Xdec, dWih, dbias, dg, 2032, 2048, 1536, 0);
    dec_act_kernel<<<4064, 256>>>();
    build_Xpred_kernel<<<4064, 256>>>();

    // pred GEMM -> row-major g_pred, then coalesced transpose into out
    gemm_mma_kernel<<<dim3(16, 166), 256, mma_smem>>>(Xpred, dfc_W, dfc_b, pred, 2032, VV, 2048, 0);
    transpose_out_kernel<<<dim3(661, 4, 16), dim3(32, 8)>>>(out);

    // loss
    loss_rows_kernel<<<2032, 256>>>(sum_ids);
    loss_final_kernel<<<1, 256>>>(out);
}

// round 17
// speedup vs baseline: 1.4097x; 1.3986x over previous
#include <cuda_runtime.h>
#include <cuda_bf16.h>
#include <cuda_fp16.h>
#include <cstdint>
#include <math.h>

#define BB 16
#define LL 512
#define TT 128
#define VV 21128
#define DD 512

// packed fp32x2 helpers (scalar gemm)
#define PACK2(d, a, b)  asm("mov.b64 %0, {%1,%2};" : "=l"(d) : "f"(a), "f"(b))
#define FMA2(acc, a, b) asm("fma.rn.f32x2 %0, %1, %2, %3;" : "=l"(acc) : "l"(a), "l"(b), "l"(acc))
#define UNPACK2(lo, hi, p) asm("mov.b64 {%0,%1}, %2;" : "=f"(lo), "=f"(hi) : "l"(p))

// ---------------------------------------------------------------------------
// Device scratch
// ---------------------------------------------------------------------------
__device__ __align__(16) float g_emb[BB * LL * DD];
__device__ __align__(16) float g_Wcat[4096 * 512];
__device__ __align__(16) float g_bcat[4096];
__device__ __align__(16) float g_xg[8192 * 4096];
__device__ __align__(16) float g_encf[BB * LL * DD];
__device__ __align__(16) float g_encb[BB * LL * DD];
__device__ __align__(16) __half g_hbh[2 * 2 * BB * DD];   // h hi halves [parity][dir][b][u]
__device__ __align__(16) __half g_hbl[2 * 2 * BB * DD];   // h lo halves
__device__ __align__(16) float g_hT[BB * 1024];
__device__ __align__(16) float g_hidden[BB * DD];
__device__ __align__(16) float g_Xatt[8192 * 1536];
__device__ __align__(16) float g_energy[8192 * 512];
__device__ __align__(16) float g_att[8192];
__device__ __align__(16) float g_a[8192];
__device__ __align__(16) float g_weighted[BB * 1024];
__device__ __align__(16) float g_embs[2032 * 512];
__device__ __align__(16) float g_Xdec[2032 * 1536];
__device__ __align__(16) float g_dbias[2048];
__device__ __align__(16) float g_dg[2032 * 2048];
__device__ __align__(16) float g_dech[2032 * 512];
__device__ __align__(16) float g_Xpred[2032 * 2048];
__device__ __align__(16) float g_pred[2032 * VV];
__device__ float g_nll[2032];
__device__ unsigned g_bar2[2];

__device__ __forceinline__ float sigf(float x) { return 1.0f / (1.0f + expf(-x)); }

__device__ __forceinline__ unsigned smem_u32(const void* p)
{
    unsigned a;
    asm("{ .reg .u64 t; cvta.to.shared.u64 t, %1; cvt.u32.u64 %0, t; }" : "=r"(a) : "l"(p));
    return a;
}

#define LDSM_X4(r0, r1, r2, r3, addr) \
    asm volatile("ldmatrix.sync.aligned.m8n8.x4.shared.b16 {%0,%1,%2,%3}, [%4];" \
                 : "=r"(r0), "=r"(r1), "=r"(r2), "=r"(r3) : "r"(addr))

#define MMA_F16(c, a, b) \
    asm volatile("mma.sync.aligned.m16n8k16.row.col.f32.f16.f16.f32 " \
                 "{%0,%1,%2,%3}, {%4,%5,%6,%7}, {%8,%9}, {%0,%1,%2,%3};" \
                 : "+f"((c)[0]), "+f"((c)[1]), "+f"((c)[2]), "+f"((c)[3]) \
                 : "r"((a)[0]), "r"((a)[1]), "r"((a)[2]), "r"((a)[3]), \
                   "r"((b)[0]), "r"((b)[1]))

// split fp32x4 -> fp16x4 hi (uint2) + fp16x4 lo (uint2)   [A operand]
__device__ __forceinline__ void split4h(const float4& v, uint2& h, uint2& l)
{
    __half2 h01 = __floats2half2_rn(v.x, v.y);
    __half2 h23 = __floats2half2_rn(v.z, v.w);
    float2 f01 = __half22float2(h01);
    float2 f23 = __half22float2(h23);
    __half2 l01 = __floats2half2_rn(v.x - f01.x, v.y - f01.y);
    __half2 l23 = __floats2half2_rn(v.z - f23.x, v.w - f23.y);
    h = make_uint2(*(unsigned*)&h01, *(unsigned*)&h23);
    l = make_uint2(*(unsigned*)&l01, *(unsigned*)&l23);
}

// fp32x4 -> fp16x4 hi only   [B operand]
__device__ __forceinline__ uint2 cvt4h(const float4& v)
{
    __half2 h01 = __floats2half2_rn(v.x, v.y);
    __half2 h23 = __floats2half2_rn(v.z, v.w);
    return make_uint2(*(unsigned*)&h01, *(unsigned*)&h23);
}

// ---------------------------------------------------------------------------
// fp16 split-precision warp-mma GEMM (2 passes):
//   C[M,N] = (A_hi + A_lo)[M,K] @ B_hi[N,K]^T + bias
//   mode 0: plain   1: tanh
// ---------------------------------------------------------------------------
__global__ void __launch_bounds__(256, 1)
gemm_mma_kernel(const float* __restrict__ A, const float* __restrict__ Bw,
                const float* __restrict__ bias, float* __restrict__ C,
                int M, int N, int K, int mode)
{
    extern __shared__ __align__(16) char smem[];
    const unsigned sbase = smem_u32(smem);
    const unsigned OFF_AH = 0, OFF_AL = 18432, OFF_BH = 36864;

    const int tid  = threadIdx.x;
    const int wid  = tid >> 5;
    const int lane = tid & 31;
    const int wm   = wid >> 2;
    const int wn   = wid & 3;
    const int row0 = blockIdx.x * 128;
    const int col0 = blockIdx.y * 128;

    float acc[4][4][4];
#pragma unroll
    for (int i = 0; i < 4; i++)
#pragma unroll
        for (int j = 0; j < 4; j++)
#pragma unroll
            for (int q = 0; q < 4; q++) acc[i][j][q] = 0.0f;

    const int a_lr = lane & 15, a_lh = lane >> 4;
    const int b_g = lane >> 3, b_l8 = lane & 7;
    const int b_rofs = (b_g >> 1) * 8 + b_l8;
    const int b_cofs = (b_g & 1) * 8;

    int srow[8], scol[8];
#pragma unroll
    for (int i = 0; i < 8; i++) {
        int idx = tid + (i << 8);
        srow[i] = idx >> 4;
        scol[i] = (idx & 15) << 2;
    }

    const float4 zf = make_float4(0.f, 0.f, 0.f, 0.f);
    float4 pa[8], pb[8];
#pragma unroll
    for (int i = 0; i < 8; i++) {
        int ar = row0 + srow[i];
        pa[i] = (ar < M) ? *(const float4*)(A + (size_t)ar * K + scol[i]) : zf;
        int br = col0 + srow[i];
        pb[i] = (br < N) ? *(const float4*)(Bw + (size_t)br * K + scol[i]) : zf;
    }

    const int nch = K >> 6;
    for (int kc = 0; kc < nch; kc++) {
        __syncthreads();
#pragma unroll
        for (int i = 0; i < 8; i++) {
            unsigned so = srow[i] * 144 + scol[i] * 2;
            uint2 h, l;
            split4h(pa[i], h, l);
            *(uint2*)(smem + OFF_AH + so) = h;
            *(uint2*)(smem + OFF_AL + so) = l;
            *(uint2*)(smem + OFF_BH + so) = cvt4h(pb[i]);
        }
        __syncthreads();

        if (kc + 1 < nch) {
            const int k0 = (kc + 1) << 6;
#pragma unroll
            for (int i = 0; i < 8; i++) {
                int ar = row0 + srow[i];
                pa[i] = (ar < M) ? *(const float4*)(A + (size_t)ar * K + k0 + scol[i]) : zf;
                int br = col0 + srow[i];
                pb[i] = (br < N) ? *(const float4*)(Bw + (size_t)br * K + k0 + scol[i]) : zf;
            }
        }

#pragma unroll
        for (int k16 = 0; k16 < 4; k16++) {
            const int kb = k16 << 4;
            unsigned aH[4][4], aL[4][4], bH[4][2];
#pragma unroll
            for (int i = 0; i < 4; i++) {
                unsigned rm = (unsigned)(wm * 64 + i * 16 + a_lr);
                unsigned off = rm * 144 + (unsigned)(kb + a_lh * 8) * 2;
                LDSM_X4(aH[i][0], aH[i][1], aH[i][2], aH[i][3], sbase + OFF_AH + off);
                LDSM_X4(aL[i][0], aL[i][1], aL[i][2], aL[i][3], sbase + OFF_AL + off);
            }
#pragma unroll
            for (int j2 = 0; j2 < 2; j2++) {
                unsigned rn = (unsigned)(wn * 32 + j2 * 16 + b_rofs);
                unsigned off = rn * 144 + (unsigned)(kb + b_cofs) * 2;
                LDSM_X4(bH[2 * j2][0], bH[2 * j2][1], bH[2 * j2 + 1][0], bH[2 * j2 + 1][1],
                        sbase + OFF_BH + off);
            }
#pragma unroll
            for (int i = 0; i < 4; i++)
#pragma unroll
                for (int j = 0; j < 4; j++) {
                    MMA_F16(acc[i][j], aH[i], bH[j]);
                    MMA_F16(acc[i][j], aL[i], bH[j]);
                }
        }
    }

    const int lm = lane >> 2;
    const int ln = (lane & 3) * 2;
#pragma unroll
    for (int i = 0; i < 4; i++) {
#pragma unroll
        for (int j = 0; j < 4; j++) {
            int nbase = col0 + wn * 32 + j * 8 + ln;
#pragma unroll
            for (int half = 0; half < 2; half++) {
                int r = row0 + wm * 64 + i * 16 + lm + half * 8;
                if (r >= M) continue;
                float v0 = acc[i][j][half * 2 + 0];
                float v1 = acc[i][j][half * 2 + 1];
                if (nbase < N) {
                    float v = v0 + __ldg(&bias[nbase]);
                    C[(size_t)r * N + nbase] = (mode == 1) ? tanhf(v) : v;
                }
                if (nbase + 1 < N) {
                    float v = v1 + __ldg(&bias[nbase + 1]);
                    C[(size_t)r * N + nbase + 1] = (mode == 1) ? tanhf(v) : v;
                }
            }
        }
    }
}

// ---------------------------------------------------------------------------
// Transpose g_pred[r= b*127+t-1][v] -> out[b][v][t]
// ---------------------------------------------------------------------------
__global__ void transpose_out_kernel(float* __restrict__ out)
{
    __shared__ float tile[32][33];
    const int b  = blockIdx.z;
    const int v0 = blockIdx.x * 32;
    const int t0 = 1 + blockIdx.y * 32;
    const int tv = threadIdx.x;
    const int tr = threadIdx.y;
#pragma unroll
    for (int i = 0; i < 4; i++) {
        int t = t0 + tr * 4 + i;
        int v = v0 + tv;
        if (t < 128 && v < VV)
            tile[tr * 4 + i][tv] = g_pred[(size_t)(b * 127 + t - 1) * VV + v];
    }
    __syncthreads();
#pragma unroll
    for (int i = 0; i < 4; i++) {
        int v = v0 + tr * 4 + i;
        int t = t0 + tv;
        if (t < 128 && v < VV)
            out[((size_t)b * VV + v) * TT + t] = tile[tv][tr * 4 + i];
    }
}

// ---------------------------------------------------------------------------
// Setup
// ---------------------------------------------------------------------------
__global__ void setup_kernel(const float* __restrict__ Wih_f, const float* __restrict__ Wih_b,
                             const float* __restrict__ bih_f, const float* __restrict__ bhh_f,
                             const float* __restrict__ bih_b, const float* __restrict__ bhh_b,
                             const float* __restrict__ dbih, const float* __restrict__ dbhh,
                             float* __restrict__ out)
{
    int i = blockIdx.x * blockDim.x + threadIdx.x;
    {
        int n  = i >> 7;
        int k4 = (i & 127) << 2;
        const float* W = (n < 2048) ? Wih_f : Wih_b;
        *(float4*)&g_Wcat[(size_t)n * 512 + k4] =
            *(const float4*)&W[(size_t)(n & 2047) * 512 + k4];
    }
    if (i < 4096)
        g_bcat[i] = (i < 2048) ? (bih_f[i] + bhh_f[i]) : (bih_b[i - 2048] + bhh_b[i - 2048]);
    if (i < 2048)
        g_dbias[i] = dbih[i] + dbhh[i];
    if (i < BB * VV)
        out[(size_t)i * TT] = 0.0f;
    if (i < 2) g_bar2[i] = 0u;
}

// ---------------------------------------------------------------------------
// Embedding gathers
// ---------------------------------------------------------------------------
__global__ void embed_doc_kernel(const int* __restrict__ ids, const float* __restrict__ E)
{
    int i = blockIdx.x * blockDim.x + threadIdx.x;
    int m = i >> 7, d4 = (i & 127) << 2;
    int id = ids[m];
    *(float4*)&g_emb[(size_t)m * 512 + d4] = *(const float4*)&E[(size_t)id * 512 + d4];
}

__global__ void embed_sum_kernel(const int* __restrict__ summ, const float* __restrict__ E)
{
    int i = blockIdx.x * blockDim.x + threadIdx.x;
    int m = i >> 7, d4 = (i & 127) << 2;
    int b = m / 127, t = m % 127;
    int id = summ[b * TT + t];
    *(float4*)&g_embs[(size_t)m * 512 + d4] = *(const float4*)&E[(size_t)id * 512 + d4];
}

// ---------------------------------------------------------------------------
// Small scalar GEMM (f32x2) for the 16-row 'hidden' layer
// ---------------------------------------------------------------------------
__global__ void __launch_bounds__(256)
gemm_tn_kernel(const float* __restrict__ A, const float* __restrict__ Bw,
               const float* __restrict__ bias, float* __restrict__ C,
               int M, int N, int K, int mode)
{
    __shared__ __align__(16) float As[2][8 * 132];
    __shared__ __align__(16) float Bs[2][8 * 132];
    const int tid = threadIdx.x;
    const int row0 = blockIdx.y * 128;
    const int col0 = blockIdx.x * 128;
    const int lr = tid >> 1;
    const int lk = (tid & 1) * 4;
    const int ty = tid >> 4, tx = tid & 15;

    unsigned long long acc2[8][4];
#pragma unroll
    for (int i = 0; i < 8; i++)
#pragma unroll
        for (int j = 0; j < 4; j++) acc2[i][j] = 0ULL;

    const int arow = row0 + lr;
    const int brow = col0 + lr;
    const bool aval = arow < M;
    const bool bval = brow < N;
    const float* Aptr = A + (size_t)arow * K + lk;
    const float* Bptr = Bw + (size_t)brow * K + lk;
    const int NT = K >> 3;

    float4 a4 = aval ? *(const float4*)Aptr : make_float4(0.f, 0.f, 0.f, 0.f);
    float4 b4 = bval ? *(const float4*)Bptr : make_float4(0.f, 0.f, 0.f, 0.f);
    As[0][(lk + 0) * 132 + lr] = a4.x; As[0][(lk + 1) * 132 + lr] = a4.y;
    As[0][(lk + 2) * 132 + lr] = a4.z; As[0][(lk + 3) * 132 + lr] = a4.w;
    Bs[0][(lk + 0) * 132 + lr] = b4.x; Bs[0][(lk + 1) * 132 + lr] = b4.y;
    Bs[0][(lk + 2) * 132 + lr] = b4.z; Bs[0][(lk + 3) * 132 + lr] = b4.w;
    __syncthreads();

    for (int t = 0; t < NT; t++) {
        const int cur = t & 1;
        if (t + 1 < NT) {
            a4 = aval ? *(const float4*)(Aptr + (size_t)(t + 1) * 8) : make_float4(0.f, 0.f, 0.f, 0.f);
            b4 = bval ? *(const float4*)(Bptr + (size_t)(t + 1) * 8) : make_float4(0.f, 0.f, 0.f, 0.f);
        }
#pragma unroll
        for (int k = 0; k < 8; k++) {
            float4 x0 = *(const float4*)&As[cur][k * 132 + ty * 8];
            float4 x1 = *(const float4*)&As[cur][k * 132 + ty * 8 + 4];
            float4 y0 = *(const float4*)&Bs[cur][k * 132 + tx * 8];
            float4 y1 = *(const float4*)&Bs[cur][k * 132 + tx * 8 + 4];
            unsigned long long rbp[4];
            PACK2(rbp[0], y0.x, y0.y);
            PACK2(rbp[1], y0.z, y0.w);
            PACK2(rbp[2], y1.x, y1.y);
            PACK2(rbp[3], y1.z, y1.w);
            float ra[8] = {x0.x, x0.y, x0.z, x0.w, x1.x, x1.y, x1.z, x1.w};
#pragma unroll
            for (int i = 0; i < 8; i++) {
                unsigned long long rad;
                PACK2(rad, ra[i], ra[i]);
                FMA2(acc2[i][0], rad, rbp[0]);
                FMA2(acc2[i][1], rad, rbp[1]);
                FMA2(acc2[i][2], rad, rbp[2]);
                FMA2(acc2[i][3], rad, rbp[3]);
            }
        }
        if (t + 1 < NT) {
            const int nxt = cur ^ 1;
            As[nxt][(lk + 0) * 132 + lr] = a4.x; As[nxt][(lk + 1) * 132 + lr] = a4.y;
            As[nxt][(lk + 2) * 132 + lr] = a4.z; As[nxt][(lk + 3) * 132 + lr] = a4.w;
            Bs[nxt][(lk + 0) * 132 + lr] = b4.x; Bs[nxt][(lk + 1) * 132 + lr] = b4.y;
            Bs[nxt][(lk + 2) * 132 + lr] = b4.z; Bs[nxt][(lk + 3) * 132 + lr] = b4.w;
            __syncthreads();
        }
    }

#pragma unroll
    for (int i = 0; i < 8; i++) {
        int r = row0 + ty * 8 + i;
        if (r >= M) continue;
#pragma unroll
        for (int jj = 0; jj < 4; jj++) {
            float lo, hi;
            UNPACK2(lo, hi, acc2[i][jj]);
            float vv[2] = {lo, hi};
#pragma unroll
            for (int q = 0; q < 2; q++) {
                int c = col0 + tx * 8 + jj * 2 + q;
                if (c >= N) continue;
                float v = vv[q] + bias[c];
                C[(size_t)r * N + c] = (mode == 1) ? tanhf(v) : v;
            }
        }
    }
}

// ---------------------------------------------------------------------------
// Persistent bidirectional LSTM with tensor-core recurrence.
// Per block per step: G[16 batches][32 gate-rows] = h[16][512] @ W[32][512]^T
// as mma m16n8k16, 3-pass fp16 split (Whi*hhi + Whi*hlo + Wlo*hhi).
// W fragments live in registers (loaded once); h staged fp16 hi/lo per step.
// smem layout (floats):
//   init: W16h halves [0..8320), W16l halves [8320..16640)
//   main: hH halves [0..4160), hL halves [4160..8320),
//         red @8320 (4608), gate_s @12928 (512), c_s @13440 (128)
// ---------------------------------------------------------------------------
__global__ void __launch_bounds__(256)
lstm_kernel(const float* __restrict__ Whh_f, const float* __restrict__ Whh_b)
{
    extern __shared__ __align__(16) float sm[];
    __half* W16h = (__half*)sm;                 // byte off 0, row stride 1040
    __half* W16l = (__half*)(sm + 8320);        // byte off 33280
    float* red    = sm + 8320;
    float* gate_s = sm + 12928;
    float* c_s    = sm + 13440;
    const unsigned sbase = smem_u32(sm);

    const int tid = threadIdx.x;
    const int blk = blockIdx.x;
    const int dir = blk >> 6;
    const int u0  = (blk & 63) * 8;
    const float* Whh = dir ? Whh_b : Whh_f;

    // ---- stage Whh as fp16 hi/lo (row = gate*8 + unit, 520-half stride) ----
    for (int t = 0; t < 64; t++) {
        int idx = tid + (t << 8);               // 0..16383
        int lrow = idx >> 9, k = idx & 511;
        int gt = lrow >> 3, j = lrow & 7;
        float w = Whh[(size_t)(gt * 512 + u0 + j) * 512 + k];
        __half whi = __float2half_rn(w);
        __half wlo = __float2half_rn(w - __half2float(whi));
        W16h[lrow * 520 + k] = whi;
        W16l[lrow * 520 + k] = wlo;
    }
    __syncthreads();

    // ---- each warp loads its B fragments into registers (k-slice ks*64) ----
    const int ks   = tid >> 5;
    const int lane = tid & 31;
    const int k0   = ks * 64;
    const int b_g = lane >> 3, b_l8 = lane & 7;
    const int b_rofs = (b_g >> 1) * 8 + b_l8;
    const int b_cofs = (b_g & 1) * 8;
    const int a_lr = lane & 15, a_lh = lane >> 4;

    unsigned bH[4][4][2], bL[4][4][2];
#pragma unroll
    for (int kc = 0; kc < 4; kc++) {
        int kb = k0 + kc * 16;
#pragma unroll
        for (int j2 = 0; j2 < 2; j2++) {
            unsigned rn = (unsigned)(j2 * 16 + b_rofs);
            unsigned offh = rn * 1040 + (unsigned)(kb + b_cofs) * 2;
            LDSM_X4(bH[kc][2 * j2][0], bH[kc][2 * j2][1],
                    bH[kc][2 * j2 + 1][0], bH[kc][2 * j2 + 1][1], sbase + offh);
            LDSM_X4(bL[kc][2 * j2][0], bL[kc][2 * j2][1],
                    bL[kc][2 * j2 + 1][0], bL[kc][2 * j2 + 1][1], sbase + 33280 + offh);
        }
    }
    __syncthreads();

    // ---- zero h stages (h(0)=0) and cell state ----
    for (int idx = tid; idx < 8320; idx += 256) sm[idx] = 0.0f;
    if (tid < 128) c_s[tid] = 0.0f;
    __syncthreads();

    unsigned* barp = &g_bar2[dir];
    const int lm = lane >> 2;
    const int ln = (lane & 3) * 2;

    for (int s = 0; s < 512; s++) {
        const int pos = dir ? (511 - s) : s;

        // ---- tensor-core matvec: this warp's 64-k slice ----
        float acc[4][4];
#pragma unroll
        for (int n = 0; n < 4; n++)
#pragma unroll
            for (int q = 0; q < 4; q++) acc[n][q] = 0.0f;

#pragma unroll
        for (int kc = 0; kc < 4; kc++) {
            const int kb = k0 + kc * 16;
            unsigned aH[4], aL[4];
            unsigned offA = (unsigned)a_lr * 1040 + (unsigned)(kb + a_lh * 8) * 2;
            LDSM_X4(aH[0], aH[1], aH[2], aH[3], sbase + offA);
            LDSM_X4(aL[0], aL[1], aL[2], aL[3], sbase + 16640 + offA);
#pragma unroll
            for (int n = 0; n < 4; n++) {
                MMA_F16(acc[n], aH, bH[kc][n]);
                MMA_F16(acc[n], aL, bH[kc][n]);
                MMA_F16(acc[n], aH, bL[kc][n]);
            }
        }
        // partials -> red[(gaterow*16 + batch)*9 + ks]
#pragma unroll
        for (int n = 0; n < 4; n++)
#pragma unroll
            for (int half = 0; half < 2; half++)
#pragma unroll
                for (int q = 0; q < 2; q++) {
                    int gaterow = n * 8 + ln + q;
                    int batch = lm + half * 8;
                    red[(gaterow * 16 + batch) * 9 + ks] = acc[n][half * 2 + q];
                }
        __syncthreads();

        // ---- reduce 8 k-slices ----
#pragma unroll
        for (int rep = 0; rep < 2; rep++) {
            int p = tid + rep * 256;
            float ssum = 0.0f;
#pragma unroll
            for (int q = 0; q < 8; q++) ssum += red[p * 9 + q];
            gate_s[p] = ssum;
        }
        __syncthreads();

        // ---- gates + state update ----
        if (tid < 128) {
            const int j = tid & 7, b = tid >> 3;
            const size_t xrow = (size_t)(b * 512 + pos) * 4096 + dir * 2048 + u0 + j;
            float gi = gate_s[(0 * 8 + j) * 16 + b] + g_xg[xrow];
            float gf = gate_s[(1 * 8 + j) * 16 + b] + g_xg[xrow + 512];
            float gg = gate_s[(2 * 8 + j) * 16 + b] + g_xg[xrow + 1024];
            float go = gate_s[(3 * 8 + j) * 16 + b] + g_xg[xrow + 1536];
            float c = sigf(gf) * c_s[tid] + sigf(gi) * tanhf(gg);
            c_s[tid] = c;
            float h = sigf(go) * tanhf(c);
            const int u = u0 + j;
            (dir ? g_encb : g_encf)[(size_t)(b * 512 + pos) * 512 + u] = h;
            __half hhi = __float2half_rn(h);
            __half hlo = __float2half_rn(h - __half2float(hhi));
            int hidx = ((s + 1) & 1) * 16384 + dir * 8192 + b * 512 + u;
            g_hbh[hidx] = hhi;
            g_hbl[hidx] = hlo;
            if (s == 511) g_hT[b * 1024 + dir * 512 + u] = h;
        }

        if (s < 511) {
            __syncthreads();
            if (tid == 0) {
                unsigned v;
                asm volatile("atom.add.release.gpu.global.u32 %0, [%1], 1;"
                             : "=r"(v) : "l"(barp) : "memory");
                v += 1u;
                const unsigned target = 64u * (unsigned)(s + 1);
                while (v < target) {
                    __nanosleep(32);
                    asm volatile("ld.acquire.gpu.global.u32 %0, [%1];"
                                 : "=r"(v) : "l"(barp) : "memory");
                }
            }
            __syncthreads();
            // ---- stage h hi/lo fp16: 16 rows x 512 halves each ----
            const int par = (s + 1) & 1;
            const __half* srch = g_hbh + par * 16384 + dir * 8192;
            const __half* srcl = g_hbl + par * 16384 + dir * 8192;
#pragma unroll
            for (int i = 0; i < 4; i++) {
                int flat = tid + (i << 8);      // 0..1023
                int row = flat >> 6, c8 = flat & 63;
                uint4 vh = __ldcg((const uint4*)(srch + row * 512) + c8);
                ((uint4*)((__half*)sm + row * 520))[c8] = vh;
                uint4 vl = __ldcg((const uint4*)(srcl + row * 512) + c8);
                ((uint4*)((__half*)(sm + 4160) + row * 520))[c8] = vl;
            }
            __syncthreads();
        }
    }
}

// ---------------------------------------------------------------------------
// Attention chain
// ---------------------------------------------------------------------------
__global__ void build_Xatt_kernel()
{
    int i = blockIdx.x * blockDim.x + threadIdx.x;
    int m = i / 384, q = i % 384;
    int col = q * 4;
    int b = m >> 9;
    float4 v;
    if (col < 512)        v = *(const float4*)&g_hidden[b * 512 + col];
    else if (col < 1024)  v = *(const float4*)&g_encf[(size_t)m * 512 + (col - 512)];
    else                  v = *(const float4*)&g_encb[(size_t)m * 512 + (col - 1024)];
    *(float4*)&g_Xatt[(size_t)m * 1536 + col] = v;
}

__global__ void attdot_kernel(const int* __restrict__ doc, const float* __restrict__ v_w)
{
    int w = (blockIdx.x * blockDim.x + threadIdx.x) >> 5;
    int lane = threadIdx.x & 31;
    const float* e = g_energy + (size_t)w * 512;
    float s = 0.0f;
    for (int k = lane; k < 512; k += 32) s += e[k] * v_w[k];
#pragma unroll
    for (int o = 16; o > 0; o >>= 1) s += __shfl_xor_sync(0xFFFFFFFFu, s, o);
    if (lane == 0) g_att[w] = (doc[w] != 0) ? s : -1e10f;
}

__global__ void softmax_kernel()
{
    __shared__ float sred[512];
    int b = blockIdx.x, tid = threadIdx.x;
    float v = g_att[b * 512 + tid];
    sred[tid] = v; __syncthreads();
    for (int o = 256; o > 0; o >>= 1) { if (tid < o) sred[tid] = fmaxf(sred[tid], sred[tid + o]); __syncthreads(); }
    float mx = sred[0]; __syncthreads();
    float e = expf(v - mx);
    sred[tid] = e; __syncthreads();
    for (int o = 256; o > 0; o >>= 1) { if (tid < o) sred[tid] += sred[tid + o]; __syncthreads(); }
    g_a[b * 512 + tid] = e / sred[0];
}

__global__ void weighted_kernel()
{
    int i = blockIdx.x * blockDim.x + threadIdx.x;
    int b = i >> 10, e = i & 1023;
    const float* enc = (e < 512) ? (g_encf + (size_t)b * 512 * 512 + e)
                                 : (g_encb + (size_t)b * 512 * 512 + (e - 512));
    const float* ap = g_a + b * 512;
    float s = 0.0f;
    for (int l = 0; l < 512; l++) s += ap[l] * enc[(size_t)l * 512];
    g_weighted[i] = s;
}

// ---------------------------------------------------------------------------
// Decoder chain
// ---------------------------------------------------------------------------
__global__ void build_Xdec_kernel()
{
    int i = blockIdx.x * blockDim.x + threadIdx.x;
    int m = i / 384, q = i % 384;
    int col = q * 4;
    int b = m / 127;
    float4 v;
    if (col < 512) v = *(const float4*)&g_embs[(size_t)m * 512 + col];
    else           v = *(const float4*)&g_weighted[b * 1024 + (col - 512)];
    *(float4*)&g_Xdec[(size_t)m * 1536 + col] = v;
}

__global__ void dec_act_kernel()
{
    int i = blockIdx.x * blockDim.x + threadIdx.x;
    int m = i >> 9, u = i & 511;
    const float* gp = g_dg + (size_t)m * 2048;
    float gi = gp[u], gg = gp[1024 + u], go = gp[1536 + u];
    float c = sigf(gi) * tanhf(gg);
    g_dech[i] = sigf(go) * tanhf(c);
}

__global__ void build_Xpred_kernel()
{
    int i = blockIdx.x * blockDim.x + threadIdx.x;
    int m = i >> 9, q = i & 511;
    int col = q * 4;
    int b = m / 127;
    float4 v;
    if (col < 512)       v = *(const float4*)&g_dech[(size_t)m * 512 + col];
    else if (col < 1536) v = *(const float4*)&g_weighted[b * 1024 + (col - 512)];
    else                 v = *(const float4*)&g_embs[(size_t)m * 512 + (col - 1536)];
    *(float4*)&g_Xpred[(size_t)m * 2048 + col] = v;
}

// ---------------------------------------------------------------------------
// Loss
// ---------------------------------------------------------------------------
__global__ void loss_rows_kernel(const int* __restrict__ summ)
{
    __shared__ float sred[256];
    const int r = blockIdx.x;
    const int tid = threadIdx.x;
    const float* row = g_pred + (size_t)r * VV;
    float mx = -1e30f;
    for (int c = tid; c < VV; c += 256) mx = fmaxf(mx, row[c]);
    sred[tid] = mx; __syncthreads();
    for (int o = 128; o > 0; o >>= 1) { if (tid < o) sred[tid] = fmaxf(sred[tid], sred[tid + o]); __syncthreads(); }
    mx = sred[0]; __syncthreads();
    float sm = 0.0f;
    for (int c = tid; c < VV; c += 256) sm += expf(row[c] - mx);
    sred[tid] = sm; __syncthreads();
    for (int o = 128; o > 0; o >>= 1) { if (tid < o) sred[tid] += sred[tid + o]; __syncthreads(); }
    if (tid == 0) {
        int b = r / 127, t = r % 127;
        int tok = summ[b * TT + t + 1];
        g_nll[r] = logf(sred[0]) + mx - row[tok];
    }
}

__global__ void loss_final_kernel(float* __restrict__ out)
{
    __shared__ float sred[256];
    int tid = threadIdx.x;
    float s = 0.0f;
    for (int r = tid; r < 2032; r += 256) s += g_nll[r];
    sred[tid] = s; __syncthreads();
    for (int o = 128; o > 0; o >>= 1) { if (tid < o) sred[tid] += sred[tid + o]; __syncthreads(); }
    if (tid == 0)
        out[(size_t)BB * VV * TT] = (sred[0] + 16.0f * logf((float)VV)) / 2048.0f;
}

// ---------------------------------------------------------------------------
// Launch
// ---------------------------------------------------------------------------
extern "C" void kernel_launch(void* const* d_in, const int* in_sizes, int n_in,
                              void* d_out, int out_size)
{
    const int*   doc_ids = (const int*)  d_in[0];
    const int*   sum_ids = (const int*)  d_in[1];
    const float* E       = (const float*)d_in[2];
    const float* Wih_f   = (const float*)d_in[3];
    const float* Whh_f   = (const float*)d_in[4];
    const float* bih_f   = (const float*)d_in[5];
    const float* bhh_f   = (const float*)d_in[6];
    const float* Wih_b   = (const float*)d_in[7];
    const float* Whh_b   = (const float*)d_in[8];
    const float* bih_b   = (const float*)d_in[9];
    const float* bhh_b   = (const float*)d_in[10];
    const float* fc_W    = (const float*)d_in[11];
    const float* fc_b    = (const float*)d_in[12];
    const float* attn_W  = (const float*)d_in[13];
    const float* attn_b  = (const float*)d_in[14];
    const float* v_w     = (const float*)d_in[15];
    const float* dWih    = (const float*)d_in[16];
    const float* dbih    = (const float*)d_in[17];
    const float* dbhh    = (const float*)d_in[18];
    const float* dfc_W   = (const float*)d_in[19];
    const float* dfc_b   = (const float*)d_in[20];
    float* out = (float*)d_out;

    const int lstm_smem = 16640 * 4;
    cudaFuncSetAttribute(lstm_kernel, cudaFuncAttributeMaxDynamicSharedMemorySize, lstm_smem);
    const int mma_smem = 55296;
    cudaFuncSetAttribute(gemm_mma_kernel, cudaFuncAttributeMaxDynamicSharedMemorySize, mma_smem);

    float *emb, *Wcat, *bcat, *xg, *hT, *hidden, *Xatt, *energy, *Xdec, *dbias, *dg, *Xpred, *pred;
    cudaGetSymbolAddress((void**)&emb,    g_emb);
    cudaGetSymbolAddress((void**)&Wcat,   g_Wcat);
    cudaGetSymbolAddress((void**)&bcat,   g_bcat);
    cudaGetSymbolAddress((void**)&xg,     g_xg);
    cudaGetSymbolAddress((void**)&hT,     g_hT);
    cudaGetSymbolAddress((void**)&hidden, g_hidden);
    cudaGetSymbolAddress((void**)&Xatt,   g_Xatt);
    cudaGetSymbolAddress((void**)&energy, g_energy);
    cudaGetSymbolAddress((void**)&Xdec,   g_Xdec);
    cudaGetSymbolAddress((void**)&dbias,  g_dbias);
    cudaGetSymbolAddress((void**)&dg,     g_dg);
    cudaGetSymbolAddress((void**)&Xpred,  g_Xpred);
    cudaGetSymbolAddress((void**)&pred,   g_pred);

    setup_kernel<<<2048, 256>>>(Wih_f, Wih_b, bih_f, bhh_f, bih_b, bhh_b, dbih, dbhh, out);
    embed_doc_kernel<<<4096, 256>>>(doc_ids, E);

    // xg = emb @ Wcat^T + bcat
    gemm_mma_kernel<<<dim3(64, 32), 256, mma_smem>>>(emb, Wcat, bcat, xg, 8192, 4096, 512, 0);

    // persistent bidirectional LSTM (tensor-core recurrence)
    lstm_kernel<<<128, 256, lstm_smem>>>(Whh_f, Whh_b);

    // hidden = tanh(hT @ fc_W^T + fc_b)
    gemm_tn_kernel<<<dim3(4, 1), 256>>>(hT, fc_W, fc_b, hidden, 16, 512, 1024, 1);

    // attention
    build_Xatt_kernel<<<12288, 256>>>();
    gemm_mma_kernel<<<dim3(64, 4), 256, mma_smem>>>(Xatt, attn_W, attn_b, energy, 8192, 512, 1536, 1);
    attdot_kernel<<<1024, 256>>>(doc_ids, v_w);
    softmax_kernel<<<16, 512>>>();
    weighted_kernel<<<64, 256>>>();

    // decoder
    embed_sum_kernel<<<1016, 256>>>(sum_ids, E);
    build_Xdec_kernel<<<3048, 256>>>();
    gemm_mma_kernel<<<dim3(16, 16), 256, mma_smem>>>(Xdec, dWih, dbias, dg, 2032, 2048, 1536, 0);
    dec_act_kernel<<<4064, 256>>>();
    build_Xpred_kernel<<<4064, 256>>>();

    // pred GEMM -> row-major g_pred, then coalesced transpose into out
    gemm_mma_kernel<<<dim3(16, 166), 256, mma_smem>>>(Xpred, dfc_W, dfc_b, pred, 2032, VV, 2048, 0);
    transpose_out_kernel<<<dim3(661, 4, 16), dim3(32, 8)>>>(out);

    // loss
    loss_rows_kernel<<<2032, 256>>>(sum_ids);
    loss_final_kernel<<<1, 256>>>(out);
}